// round 13
// baseline (speedup 1.0000x reference)
#include <cuda_runtime.h>
#include <cuda_bf16.h>
#include <math.h>
#include <stdint.h>

// Problem constants
#define BB 2
#define SS 2048
#define EE 768
#define FF 3072
#define RR 4
#define TT 128
#define HH 12
#define HD 64
#define HID 128
#define MM (BB*SS)          // 4096 tokens

// ---------------- scratch (device globals; no cudaMalloc allowed) ----------
__device__ float g_x1  [MM*EE];
__device__ float g_qkv [MM*3*EE];
__device__ float g_ctx [MM*EE];
__device__ float g_src2[MM*EE];
__device__ float g_x2  [MM*EE];
__device__ float g_hA  [MM*HID];
__device__ float g_hB  [MM*HID];
__device__ float g_WBt [(RR*HID+RR)*EE];
__device__ float g_v   [MM*(RR*HID+RR)];
__device__ float g_int [MM*RR];
__device__ float g_u   [MM*RR*HID];
__device__ float g_h   [MM*FF];
// rounded copies of GEMM operands
__device__ float g_r_task  [MM*TT];
__device__ float g_r_inproj[3*EE*EE];
__device__ float g_r_outproj[EE*EE];
__device__ float g_r_ffn1  [FF*EE];
__device__ float g_r_ffn2  [EE*FF];
__device__ float g_r_hAw2  [FF*RR*HID];
__device__ float g_r_hw1   [2*HID*TT];

// ---------------- helpers ---------------------------------------------------
__device__ __forceinline__ unsigned f2tf32(float f) {
    unsigned u;
    asm("cvt.rna.tf32.f32 %0, %1;" : "=r"(u) : "f"(f));
    return u;
}
__device__ __forceinline__ float rnd(float f) { return __uint_as_float(f2tf32(f)); }

__device__ __forceinline__ unsigned packbf(float hi, float lo) {
    unsigned r;
    asm("cvt.rn.bf16x2.f32 %0, %1, %2;" : "=r"(r) : "f"(hi), "f"(lo));
    return r;
}

__device__ __forceinline__ void mma_tf32(float c[4], const unsigned a[4], const unsigned b[2]) {
    asm volatile(
        "mma.sync.aligned.m16n8k8.row.col.f32.tf32.tf32.f32 "
        "{%0,%1,%2,%3}, {%4,%5,%6,%7}, {%8,%9}, {%0,%1,%2,%3};\n"
        : "+f"(c[0]), "+f"(c[1]), "+f"(c[2]), "+f"(c[3])
        : "r"(a[0]), "r"(a[1]), "r"(a[2]), "r"(a[3]), "r"(b[0]), "r"(b[1]));
}

__device__ __forceinline__ void mma_bf16(float c[4], const unsigned a[4], unsigned b0, unsigned b1) {
    asm volatile(
        "mma.sync.aligned.m16n8k16.row.col.f32.bf16.bf16.f32 "
        "{%0,%1,%2,%3}, {%4,%5,%6,%7}, {%8,%9}, {%0,%1,%2,%3};\n"
        : "+f"(c[0]), "+f"(c[1]), "+f"(c[2]), "+f"(c[3])
        : "r"(a[0]), "r"(a[1]), "r"(a[2]), "r"(a[3]), "r"(b0), "r"(b1));
}

__device__ __forceinline__ void cp16(unsigned dst, const float* src) {
    asm volatile("cp.async.cg.shared.global [%0], [%1], 16;\n" :: "r"(dst), "l"(src));
}
__device__ __forceinline__ void cp16z(unsigned dst, const float* src, int sz) {
    asm volatile("cp.async.cg.shared.global [%0], [%1], 16, %2;\n" :: "r"(dst), "l"(src), "r"(sz));
}
__device__ __forceinline__ void cp_commit() { asm volatile("cp.async.commit_group;\n"); }
__device__ __forceinline__ void cp_wait0()  { asm volatile("cp.async.wait_group 0;\n"); }
__device__ __forceinline__ void cp_wait1()  { asm volatile("cp.async.wait_group 1;\n"); }

// ---------------- batched rounding pass (all weights, one launch) ----------
struct RTab {
    const float* s[8];
    float* d[8];
    int end[8];          // cumulative end, in float4 units
};

__global__ void __launch_bounds__(256) round_all(RTab t, int total4)
{
    int i = blockIdx.x * 256 + threadIdx.x;
    if (i >= total4) return;
    int j = 0;
    while (i >= t.end[j]) j++;
    int off = i - (j ? t.end[j - 1] : 0);
    float4 v = ((const float4*)t.s[j])[off];
    v.x = rnd(v.x); v.y = rnd(v.y); v.z = rnd(v.z); v.w = rnd(v.w);
    ((float4*)t.d[j])[off] = v;
}

// ---------------- rmsnorm (output rounded to tf32) --------------------------
__global__ void __launch_bounds__(256) rmsnorm_kernel(
    const float* __restrict__ x, const float* __restrict__ w, float* __restrict__ y)
{
    int row = blockIdx.x;
    const float* xr = x + (size_t)row * EE;
    float vals[3];
    float s = 0.f;
#pragma unroll
    for (int i = 0; i < 3; i++) {
        vals[i] = xr[threadIdx.x + i * 256];
        s += vals[i] * vals[i];
    }
#pragma unroll
    for (int o = 16; o; o >>= 1) s += __shfl_down_sync(0xffffffffu, s, o);
    __shared__ float red[8];
    if ((threadIdx.x & 31) == 0) red[threadIdx.x >> 5] = s;
    __syncthreads();
    if (threadIdx.x < 8) {
        float t = red[threadIdx.x];
#pragma unroll
        for (int o = 4; o; o >>= 1) t += __shfl_down_sync(0xffu, t, o);
        if (threadIdx.x == 0) red[0] = t;
    }
    __syncthreads();
    float r = rsqrtf(red[0] * (1.0f / EE) + 1.1920929e-7f);
    float* yr = y + (size_t)row * EE;
#pragma unroll
    for (int i = 0; i < 3; i++) {
        int c = threadIdx.x + i * 256;
        yr[c] = rnd(vals[i] * r * w[c]);
    }
}

// ---------------- tf32 GEMM: 128 threads, 4 warps (2x2), 64m x NT/2 n per warp
// C = A @ W^T over K, then optionally + A2 @ B2^T over K2 (dual-K accumulate)
// flags bit0: relu, bit1: round output to tf32
// blockIdx.z==1 selects (Bz,biasz,Cz) alternate problem (same A/M/N/K)
#define ST 36
#define ATILE (128*ST)      // 4608 floats

template<int NT>
__global__ void __launch_bounds__(128, 2) mma_gemm(
    const float* __restrict__ A, const float* __restrict__ B, float* __restrict__ C,
    const float* __restrict__ bias, const float* __restrict__ res,
    const float* __restrict__ inter4, const float* __restrict__ b2,
    const float* __restrict__ A2, const float* __restrict__ B2,
    int K2, int lda2, int ldb2,
    const float* __restrict__ Bz, const float* __restrict__ biasz, float* __restrict__ Cz,
    int M, int N, int K, int lda, int ldb, int ldc, int flags)
{
    constexpr int BTILE = NT * ST;
    constexpr int STG = ATILE + BTILE;
    constexpr int NWT = NT / 16;     // n-subtiles per warp (8 or 4)

    extern __shared__ float dyn[];
    if (blockIdx.z == 1) { B = Bz; bias = biasz; C = Cz; }

    const int tid  = threadIdx.x;
    const int lane = tid & 31, warp = tid >> 5;
    const int g = lane >> 2, t4 = lane & 3;
    const int wm = (warp >> 1) * 64;           // 0 or 64
    const int wn = (warp & 1) * (NT / 2);      // 0 or NT/2
    const int mBase = blockIdx.y * 128, nBase = blockIdx.x * NT;
    const int lr = tid >> 3;            // 0..15
    const int kA = (tid & 7) * 4;       // 0,4,..,28

    const unsigned sb = (unsigned)__cvta_generic_to_shared(dyn);

    const int n1 = K >> 5, n2 = K2 >> 5, nT = n1 + n2;

    float acc[4][NWT][4];
#pragma unroll
    for (int i = 0; i < 4; i++)
#pragma unroll
        for (int j = 0; j < NWT; j++)
#pragma unroll
            for (int c = 0; c < 4; c++) acc[i][j][c] = 0.f;

    auto issue = [&](int t, int buf) {
        const float* Ab; const float* Bb; int la, lb, k0;
        if (t < n1) { Ab = A;  Bb = B;  la = lda;  lb = ldb;  k0 = t * 32; }
        else        { Ab = A2; Bb = B2; la = lda2; lb = ldb2; k0 = (t - n1) * 32; }
#pragma unroll
        for (int r = 0; r < 8; r++) {
            int row = lr + 16 * r;
            const float* ap = Ab + (size_t)(mBase + row) * la + k0 + kA;
            cp16(sb + (buf * STG + row * ST + kA) * 4, ap);
        }
#pragma unroll
        for (int r = 0; r < NT / 16; r++) {
            int row = lr + 16 * r;
            bool ok = (nBase + row) < N;
            const float* bp = ok ? (Bb + (size_t)(nBase + row) * lb + k0 + kA) : Bb;
            cp16z(sb + (buf * STG + ATILE + row * ST + kA) * 4, bp, ok ? 16 : 0);
        }
        cp_commit();
    };

    issue(0, 0);
    if (nT > 1) issue(1, 1);

    for (int t = 0; t < nT; t++) {
        if (t < nT - 1) cp_wait1(); else cp_wait0();
        __syncthreads();
        if (t + 2 < nT) issue(t + 2, (t + 2) % 3);

        const float* As = dyn + (t % 3) * STG;
        const float* Bs = As + ATILE;
#pragma unroll
        for (int kk = 0; kk < 4; kk++) {
            const int kb = kk * 8;
            unsigned a[4][4], b[NWT][2];
#pragma unroll
            for (int mt = 0; mt < 4; mt++) {
                int mr = wm + mt * 16 + g;
                a[mt][0] = __float_as_uint(As[mr * ST + kb + t4]);
                a[mt][1] = __float_as_uint(As[(mr + 8) * ST + kb + t4]);
                a[mt][2] = __float_as_uint(As[mr * ST + kb + t4 + 4]);
                a[mt][3] = __float_as_uint(As[(mr + 8) * ST + kb + t4 + 4]);
            }
#pragma unroll
            for (int nt = 0; nt < NWT; nt++) {
                int nc = wn + nt * 8 + g;
                b[nt][0] = __float_as_uint(Bs[nc * ST + kb + t4]);
                b[nt][1] = __float_as_uint(Bs[nc * ST + kb + t4 + 4]);
            }
#pragma unroll
            for (int mt = 0; mt < 4; mt++)
#pragma unroll
                for (int nt = 0; nt < NWT; nt++)
                    mma_tf32(acc[mt][nt], a[mt], b[nt]);
        }
    }

    const bool relu = flags & 1;
    const bool roundC = flags & 2;
#pragma unroll
    for (int mt = 0; mt < 4; mt++) {
#pragma unroll
        for (int half = 0; half < 2; half++) {
            int m = mBase + wm + mt * 16 + g + half * 8;
            float i0 = 0.f, i1 = 0.f, i2 = 0.f, i3 = 0.f;
            if (inter4) {
                const float* ip = inter4 + (size_t)m * 4;
                i0 = ip[0]; i1 = ip[1]; i2 = ip[2]; i3 = ip[3];
            }
#pragma unroll
            for (int nt = 0; nt < NWT; nt++) {
#pragma unroll
                for (int c = 0; c < 2; c++) {
                    int n = nBase + wn + nt * 8 + 2 * t4 + c;
                    if (n < N) {
                        float v = acc[mt][nt][half * 2 + c];
                        if (bias) v += bias[n];
                        if (res)  v += res[(size_t)m * ldc + n];
                        if (b2) {
                            const float* bp = b2 + (size_t)n * 4;
                            v += i0 * bp[0] + i1 * bp[1] + i2 * bp[2] + i3 * bp[3];
                        }
                        if (relu) v = fmaxf(v, 0.f);
                        if (roundC) v = rnd(v);
                        C[(size_t)m * ldc + n] = v;
                    }
                }
            }
        }
    }
}

// ---------------- flash attention --------------------------------------------
// 128 threads = 4 warps; each warp owns 32 query rows (two 16-row MMA halves)
// sharing the same K/V fragment loads. QK and PV both bf16 m16n8k16.
#define QP 68
#define VP 72
#define KVST (64*QP + 64*VP)   // 8960 floats per stage
#define FSTAGES 3
__global__ void __launch_bounds__(128, 2) flash_attn(
    const float* __restrict__ qkv, float* __restrict__ ctx)
{
    extern __shared__ float pool[];
    const unsigned sb = (unsigned)__cvta_generic_to_shared(pool);

    const int z = blockIdx.y, b = z / HH, h = z % HH;
    const float* base = qkv + (size_t)b * SS * 3 * EE + h * HD;
    const int q0 = blockIdx.x * 128;
    const int tid = threadIdx.x, lane = tid & 31, warp = tid >> 5;
    const int g = lane >> 2, t4 = lane & 3;
    const float qscale = 0.125f * 1.4426950408889634f;  // 1/sqrt(64) * log2(e)

    // ---- stage Q (scaled) through smem: 128 rows x 64 cols
#pragma unroll
    for (int r = 0; r < 16; r++) {
        int idx = tid + r * 128;           // 0..2047 float4 slots
        int row = idx >> 4, c4 = (idx & 15) * 4;
        float4 v = *(const float4*)(base + (size_t)(q0 + row) * 3 * EE + c4);
        float4 w;
        w.x = v.x * qscale;
        w.y = v.y * qscale;
        w.z = v.z * qscale;
        w.w = v.w * qscale;
        *(float4*)(pool + row * QP + c4) = w;
    }
    __syncthreads();
    // bf16-packed Q fragments for m16n8k16 (4 k-steps of 16)
    unsigned qfA[4][4], qfB[4][4];
    const int wq = warp * 32;
#pragma unroll
    for (int kc = 0; kc < 4; kc++) {
        const int kb = kc * 16 + 2 * t4;
#pragma unroll
        for (int half = 0; half < 2; half++) {
            unsigned (&qf)[4][4] = half ? qfB : qfA;
            int r0 = wq + half * 16 + g;
            float2 p0 = *(const float2*)(pool + r0 * QP + kb);
            float2 p1 = *(const float2*)(pool + (r0 + 8) * QP + kb);
            float2 p2 = *(const float2*)(pool + r0 * QP + kb + 8);
            float2 p3 = *(const float2*)(pool + (r0 + 8) * QP + kb + 8);
            qf[kc][0] = packbf(p0.y, p0.x);
            qf[kc][1] = packbf(p1.y, p1.x);
            qf[kc][2] = packbf(p2.y, p2.x);
            qf[kc][3] = packbf(p3.y, p3.x);
        }
    }
    __syncthreads();

    float oA[8][4], oB[8][4];
#pragma unroll
    for (int v = 0; v < 8; v++)
#pragma unroll
        for (int c = 0; c < 4; c++) { oA[v][c] = 0.f; oB[v][c] = 0.f; }
    float lA0 = 0.f, lA1 = 0.f, lB0 = 0.f, lB1 = 0.f;

    const int frow = tid >> 4, fseg = (tid & 15) * 4;   // 8 rows/thread, 16 thr/row

    auto issue_kv = [&](int kt, int buf) {
#pragma unroll
        for (int r = 0; r < 8; r++) {
            int row = frow + r * 8;
            const float* kp = base + EE     + (size_t)(kt * 64 + row) * 3 * EE + fseg;
            const float* vp = base + 2 * EE + (size_t)(kt * 64 + row) * 3 * EE + fseg;
            cp16(sb + (buf * KVST + row * QP + fseg) * 4, kp);
            cp16(sb + (buf * KVST + 64 * QP + row * VP + fseg) * 4, vp);
        }
        cp_commit();
    };

    const int NKT = SS / 64;
    issue_kv(0, 0);
    issue_kv(1, 1);

    for (int kt = 0; kt < NKT; kt++) {
        if (kt < NKT - 1) cp_wait1(); else cp_wait0();
        __syncthreads();
        if (kt + 2 < NKT) issue_kv(kt + 2, (kt + 2) % FSTAGES);

        const float* Ks = pool + (kt % FSTAGES) * KVST;
        const float* Vs = Ks + 64 * QP;

        // ---- scores (bf16 m16n8k16), sharing K fragments across both halves
        float sA[8][4], sB[8][4];
#pragma unroll
        for (int j = 0; j < 8; j++)
#pragma unroll
            for (int c = 0; c < 4; c++) { sA[j][c] = 0.f; sB[j][c] = 0.f; }
#pragma unroll
        for (int j = 0; j < 8; j++) {
            const float* kr = Ks + (j * 8 + g) * QP + 2 * t4;
#pragma unroll
            for (int kc = 0; kc < 4; kc++) {
                float2 p0 = *(const float2*)(kr + kc * 16);
                float2 p1 = *(const float2*)(kr + kc * 16 + 8);
                unsigned b0 = packbf(p0.y, p0.x);
                unsigned b1 = packbf(p1.y, p1.x);
                mma_bf16(sA[j], qfA[kc], b0, b1);
                mma_bf16(sB[j], qfB[kc], b0, b1);
            }
        }

        // ---- max-free softmax: p = exp2(s) (scores bounded; fp32-safe)
#pragma unroll
        for (int j = 0; j < 8; j++) {
            sA[j][0] = exp2f(sA[j][0]); sA[j][1] = exp2f(sA[j][1]);
            sA[j][2] = exp2f(sA[j][2]); sA[j][3] = exp2f(sA[j][3]);
            lA0 += sA[j][0] + sA[j][1];
            lA1 += sA[j][2] + sA[j][3];
            sB[j][0] = exp2f(sB[j][0]); sB[j][1] = exp2f(sB[j][1]);
            sB[j][2] = exp2f(sB[j][2]); sB[j][3] = exp2f(sB[j][3]);
            lB0 += sB[j][0] + sB[j][1];
            lB1 += sB[j][2] + sB[j][3];
        }

        // ---- P.V in bf16 m16n8k16, sharing V fragments between halves
#pragma unroll
        for (int j2 = 0; j2 < 4; j2++) {
            unsigned paA[4], paB[4];
            paA[0] = packbf(sA[2 * j2][1],     sA[2 * j2][0]);
            paA[1] = packbf(sA[2 * j2][3],     sA[2 * j2][2]);
            paA[2] = packbf(sA[2 * j2 + 1][1], sA[2 * j2 + 1][0]);
            paA[3] = packbf(sA[2 * j2 + 1][3], sA[2 * j2 + 1][2]);
            paB[0] = packbf(sB[2 * j2][1],     sB[2 * j2][0]);
            paB[1] = packbf(sB[2 * j2][3],     sB[2 * j2][2]);
            paB[2] = packbf(sB[2 * j2 + 1][1], sB[2 * j2 + 1][0]);
            paB[3] = packbf(sB[2 * j2 + 1][3], sB[2 * j2 + 1][2]);
            const float* vr0 = Vs + (j2 * 16 + 2 * t4) * VP;
            const float* vr1 = vr0 + VP;
            const float* vr2 = vr0 + 8 * VP;
            const float* vr3 = vr2 + VP;
#pragma unroll
            for (int v = 0; v < 8; v++) {
                int d = v * 8 + g;
                unsigned b0 = packbf(vr1[d], vr0[d]);
                unsigned b1 = packbf(vr3[d], vr2[d]);
                mma_bf16(oA[v], paA, b0, b1);
                mma_bf16(oB[v], paB, b0, b1);
            }
        }
    }

    // ---- finalize (rounded: ctx feeds out_proj GEMM)
    lA0 += __shfl_xor_sync(0xffffffffu, lA0, 1);
    lA0 += __shfl_xor_sync(0xffffffffu, lA0, 2);
    lA1 += __shfl_xor_sync(0xffffffffu, lA1, 1);
    lA1 += __shfl_xor_sync(0xffffffffu, lA1, 2);
    lB0 += __shfl_xor_sync(0xffffffffu, lB0, 1);
    lB0 += __shfl_xor_sync(0xffffffffu, lB0, 2);
    lB1 += __shfl_xor_sync(0xffffffffu, lB1, 1);
    lB1 += __shfl_xor_sync(0xffffffffu, lB1, 2);
    float iA0 = 1.f / lA0, iA1 = 1.f / lA1, iB0 = 1.f / lB0, iB1 = 1.f / lB1;
    int row0 = q0 + wq + g;
    float* c0p = ctx + ((size_t)(b * SS + row0))      * EE + h * HD;
    float* c1p = ctx + ((size_t)(b * SS + row0 + 8))  * EE + h * HD;
    float* c2p = ctx + ((size_t)(b * SS + row0 + 16)) * EE + h * HD;
    float* c3p = ctx + ((size_t)(b * SS + row0 + 24)) * EE + h * HD;
#pragma unroll
    for (int v = 0; v < 8; v++) {
        int col = v * 8 + 2 * t4;
        *(float2*)(c0p + col) = make_float2(rnd(oA[v][0] * iA0), rnd(oA[v][1] * iA0));
        *(float2*)(c1p + col) = make_float2(rnd(oA[v][2] * iA1), rnd(oA[v][3] * iA1));
        *(float2*)(c2p + col) = make_float2(rnd(oB[v][0] * iB0), rnd(oB[v][1] * iB0));
        *(float2*)(c3p + col) = make_float2(rnd(oB[v][2] * iB1), rnd(oB[v][3] * iB1));
    }
}

// ---------------- small helper kernels -------------------------------------
__global__ void build_WBt(const float* __restrict__ hB_w2,
                          const float* __restrict__ hB_b2,
                          float* __restrict__ WBt)
{
    int idx = blockIdx.x * 256 + threadIdx.x;
    if (idx >= (RR * HID + RR) * EE) return;
    int n = idx / EE, e = idx % EE;
    float val;
    if (n < RR * HID) {
        int r = n >> 7, h = n & 127;
        val = hB_w2[((size_t)(r * EE + e)) * HID + h];
    } else {
        val = hB_b2[(n - RR * HID) * EE + e];
    }
    WBt[idx] = rnd(val);
}

__global__ void __launch_bounds__(256) interu_kernel(
    const float* __restrict__ v, const float* __restrict__ hB,
    const float* __restrict__ hA, float* __restrict__ inter, float* __restrict__ u)
{
    int wtok = (blockIdx.x * 256 + threadIdx.x) >> 5;
    int lane = threadIdx.x & 31;
    if (wtok >= MM) return;
    const float* vr = v + (size_t)wtok * (RR * HID + RR);
    const float* br = hB + (size_t)wtok * HID;
    float hb[4], ha[4];
#pragma unroll
    for (int j = 0; j < 4; j++) {
        hb[j] = br[lane + j * 32];
        ha[j] = hA[(size_t)wtok * HID + lane + j * 32];
    }
    float iv[RR];
#pragma unroll
    for (int r = 0; r < RR; r++) {
        float s = 0.f;
#pragma unroll
        for (int j = 0; j < 4; j++) s += hb[j] * vr[r * HID + lane + j * 32];
#pragma unroll
        for (int o = 16; o; o >>= 1) s += __shfl_xor_sync(0xffffffffu, s, o);
        iv[r] = s + vr[RR * HID + r];
    }
    if (lane < RR) inter[wtok * RR + lane] = iv[lane];
    float* ur = u + (size_t)wtok * RR * HID;
#pragma unroll
    for (int r = 0; r < RR; r++)
#pragma unroll
        for (int j = 0; j < 4; j++)
            ur[r * HID + lane + j * 32] = rnd(iv[r] * ha[j]);
}

// ---------------- launch ----------------------------------------------------
extern "C" void kernel_launch(void* const* d_in, const int* in_sizes, int n_in,
                              void* d_out, int out_size)
{
    const float* src       = (const float*)d_in[0];
    const float* task      = (const float*)d_in[1];
    const float* norm1_w   = (const float*)d_in[2];
    const float* norm2_w   = (const float*)d_in[3];
    const float* in_proj_w = (const float*)d_in[4];
    const float* out_proj_w= (const float*)d_in[5];
    const float* ffn1_w    = (const float*)d_in[6];
    const float* ffn1_b    = (const float*)d_in[7];
    const float* ffn2_w    = (const float*)d_in[8];
    const float* ffn2_b    = (const float*)d_in[9];
    const float* hA_w1     = (const float*)d_in[10];
    const float* hA_b1     = (const float*)d_in[11];
    const float* hA_w2     = (const float*)d_in[12];
    const float* hA_b2     = (const float*)d_in[13];
    const float* hB_w1     = (const float*)d_in[14];
    const float* hB_b1     = (const float*)d_in[15];
    const float* hB_w2     = (const float*)d_in[16];
    const float* hB_b2     = (const float*)d_in[17];
    float* out = (float*)d_out;

    float *x1, *qkv, *ctx, *src2, *x2, *hA, *hB, *WBt, *v, *inter, *u, *hbuf;
    float *r_task, *r_inproj, *r_outproj, *r_ffn1, *r_ffn2, *r_hAw2, *r_hw1;
    cudaGetSymbolAddress((void**)&x1,   g_x1);
    cudaGetSymbolAddress((void**)&qkv,  g_qkv);
    cudaGetSymbolAddress((void**)&ctx,  g_ctx);
    cudaGetSymbolAddress((void**)&src2, g_src2);
    cudaGetSymbolAddress((void**)&x2,   g_x2);
    cudaGetSymbolAddress((void**)&hA,   g_hA);
    cudaGetSymbolAddress((void**)&hB,   g_hB);
    cudaGetSymbolAddress((void**)&WBt,  g_WBt);
    cudaGetSymbolAddress((void**)&v,    g_v);
    cudaGetSymbolAddress((void**)&inter,g_int);
    cudaGetSymbolAddress((void**)&u,    g_u);
    cudaGetSymbolAddress((void**)&hbuf, g_h);
    cudaGetSymbolAddress((void**)&r_task,   g_r_task);
    cudaGetSymbolAddress((void**)&r_inproj, g_r_inproj);
    cudaGetSymbolAddress((void**)&r_outproj,g_r_outproj);
    cudaGetSymbolAddress((void**)&r_ffn1,   g_r_ffn1);
    cudaGetSymbolAddress((void**)&r_ffn2,   g_r_ffn2);
    cudaGetSymbolAddress((void**)&r_hAw2,   g_r_hAw2);
    cudaGetSymbolAddress((void**)&r_hw1,    g_r_hw1);

    const int DS128 = 3 * (ATILE + 128 * ST) * 4;   // 110592 B
    const int DS64  = 3 * (ATILE + 64 * ST) * 4;    //  82944 B
    const int FS = FSTAGES * KVST * 4;              // 107520 B
    cudaFuncSetAttribute(mma_gemm<128>, cudaFuncAttributeMaxDynamicSharedMemorySize, DS128);
    cudaFuncSetAttribute(mma_gemm<64>,  cudaFuncAttributeMaxDynamicSharedMemorySize, DS64);
    cudaFuncSetAttribute(flash_attn,    cudaFuncAttributeMaxDynamicSharedMemorySize, FS);

    // 0) pre-round all GEMM operands to tf32 (one launch)
    {
        RTab t;
        const float* ss[8] = {task, in_proj_w, out_proj_w, ffn1_w, ffn2_w, hA_w2, hA_w1, hB_w1};
        float* dd[8] = {r_task, r_inproj, r_outproj, r_ffn1, r_ffn2, r_hAw2, r_hw1, r_hw1 + HID * TT};
        int nn[8] = {MM * TT / 4, 3 * EE * EE / 4, EE * EE / 4, FF * EE / 4,
                     EE * FF / 4, FF * RR * HID / 4, HID * TT / 4, HID * TT / 4};
        int cum = 0;
        for (int j = 0; j < 8; j++) { t.s[j] = ss[j]; t.d[j] = dd[j]; cum += nn[j]; t.end[j] = cum; }
        round_all<<<(cum + 255) / 256, 256>>>(t, cum);
    }

    // 1) x1 = rmsnorm(src, norm1_w) (rounded)
    rmsnorm_kernel<<<MM, 256>>>(src, norm1_w, x1);

    // 2) qkv = x1 @ in_proj^T (rounded out)
    mma_gemm<128><<<dim3(18, 32, 1), 128, DS128>>>(
        x1, r_inproj, qkv, nullptr, nullptr, nullptr, nullptr,
        nullptr, nullptr, 0, 0, 0, nullptr, nullptr, nullptr,
        MM, 3 * EE, EE, EE, EE, 3 * EE, 2);

    // 3) flash attention -> ctx (rounded); 128 threads, 4 warps x 32 q-rows
    flash_attn<<<dim3(SS / 128, BB * HH), 128, FS>>>(qkv, ctx);

    // 4) src2 = src + ctx @ out_proj^T  (N=768, NT=64 -> 384 CTAs)
    mma_gemm<64><<<dim3(12, 32, 1), 128, DS64>>>(
        ctx, r_outproj, src2, nullptr, src, nullptr, nullptr,
        nullptr, nullptr, 0, 0, 0, nullptr, nullptr, nullptr,
        MM, EE, EE, EE, EE, EE, 0);

    // 5) x2 = rmsnorm(src2) (rounded)
    rmsnorm_kernel<<<MM, 256>>>(src2, norm2_w, x2);

    // 6) hypernet hiddens hA & hB in one launch (z selects problem; NT=64 -> 128 CTAs)
    mma_gemm<64><<<dim3(2, 32, 2), 128, DS64>>>(
        r_task, r_hw1, hA, hA_b1, nullptr, nullptr, nullptr,
        nullptr, nullptr, 0, 0, 0,
        r_hw1 + HID * TT, hB_b1, hB,
        MM, HID, TT, TT, TT, HID, 1);

    // 7) rearranged B-side weights (rounded)
    build_WBt<<<((RR * HID + RR) * EE + 255) / 256, 256>>>(hB_w2, hB_b2, WBt);

    // 8) v = x2 @ WBt^T  [4096, 516]  (NT=64 -> 288 CTAs)
    mma_gemm<64><<<dim3(9, 32, 1), 128, DS64>>>(
        x2, WBt, v, nullptr, nullptr, nullptr, nullptr,
        nullptr, nullptr, 0, 0, 0, nullptr, nullptr, nullptr,
        MM, RR * HID + RR, EE, EE, EE, RR * HID + RR, 0);

    // 9) inter + u (rounded)
    interu_kernel<<<MM / 8, 256>>>(v, hB, hA, inter, u);

    // 10) fused FFN1 + LoRA expand: hbuf = relu(x2@ffn1^T + u@hAw2^T + ffn1_b + lora_b), rounded
    mma_gemm<128><<<dim3(24, 32, 1), 128, DS128>>>(
        x2, r_ffn1, hbuf, ffn1_b, nullptr, inter, hA_b2,
        u, r_hAw2, RR * HID, RR * HID, RR * HID,
        nullptr, nullptr, nullptr,
        MM, FF, EE, EE, EE, FF, 3);

    // 11) out = src2 + hbuf @ ffn2^T + ffn2_b  (N=768, NT=64 -> 384 CTAs)
    mma_gemm<64><<<dim3(12, 32, 1), 128, DS64>>>(
        hbuf, r_ffn2, out, ffn2_b, src2, nullptr, nullptr,
        nullptr, nullptr, 0, 0, 0, nullptr, nullptr, nullptr,
        MM, EE, FF, FF, FF, EE, 0);
}

// round 14
// speedup vs baseline: 1.0377x; 1.0377x over previous
#include <cuda_runtime.h>
#include <cuda_bf16.h>
#include <math.h>
#include <stdint.h>

// Problem constants
#define BB 2
#define SS 2048
#define EE 768
#define FF 3072
#define RR 4
#define TT 128
#define HH 12
#define HD 64
#define HID 128
#define MM (BB*SS)          // 4096 tokens

// ---------------- scratch (device globals; no cudaMalloc allowed) ----------
__device__ float g_x1  [MM*EE];
__device__ float g_qkv [MM*3*EE];
__device__ float g_ctx [MM*EE];
__device__ float g_src2[MM*EE];
__device__ float g_x2  [MM*EE];
__device__ float g_hA  [MM*HID];
__device__ float g_hB  [MM*HID];
__device__ float g_WBt [(RR*HID+RR)*EE];
__device__ float g_v   [MM*(RR*HID+RR)];
__device__ float g_int [MM*RR];
__device__ float g_u   [MM*RR*HID];
__device__ float g_h   [MM*FF];
// rounded copies of GEMM operands
__device__ float g_r_task  [MM*TT];
__device__ float g_r_inproj[3*EE*EE];
__device__ float g_r_outproj[EE*EE];
__device__ float g_r_ffn1  [FF*EE];
__device__ float g_r_ffn2  [EE*FF];
__device__ float g_r_hAw2  [FF*RR*HID];
__device__ float g_r_hw1   [2*HID*TT];

// ---------------- helpers ---------------------------------------------------
__device__ __forceinline__ unsigned f2tf32(float f) {
    unsigned u;
    asm("cvt.rna.tf32.f32 %0, %1;" : "=r"(u) : "f"(f));
    return u;
}
__device__ __forceinline__ float rnd(float f) { return __uint_as_float(f2tf32(f)); }

__device__ __forceinline__ unsigned packbf(float hi, float lo) {
    unsigned r;
    asm("cvt.rn.bf16x2.f32 %0, %1, %2;" : "=r"(r) : "f"(hi), "f"(lo));
    return r;
}

__device__ __forceinline__ void mma_tf32(float c[4], const unsigned a[4], const unsigned b[2]) {
    asm volatile(
        "mma.sync.aligned.m16n8k8.row.col.f32.tf32.tf32.f32 "
        "{%0,%1,%2,%3}, {%4,%5,%6,%7}, {%8,%9}, {%0,%1,%2,%3};\n"
        : "+f"(c[0]), "+f"(c[1]), "+f"(c[2]), "+f"(c[3])
        : "r"(a[0]), "r"(a[1]), "r"(a[2]), "r"(a[3]), "r"(b[0]), "r"(b[1]));
}

__device__ __forceinline__ void mma_bf16(float c[4], const unsigned a[4], unsigned b0, unsigned b1) {
    asm volatile(
        "mma.sync.aligned.m16n8k16.row.col.f32.bf16.bf16.f32 "
        "{%0,%1,%2,%3}, {%4,%5,%6,%7}, {%8,%9}, {%0,%1,%2,%3};\n"
        : "+f"(c[0]), "+f"(c[1]), "+f"(c[2]), "+f"(c[3])
        : "r"(a[0]), "r"(a[1]), "r"(a[2]), "r"(a[3]), "r"(b0), "r"(b1));
}

__device__ __forceinline__ void cp16(unsigned dst, const float* src) {
    asm volatile("cp.async.cg.shared.global [%0], [%1], 16;\n" :: "r"(dst), "l"(src));
}
__device__ __forceinline__ void cp16z(unsigned dst, const float* src, int sz) {
    asm volatile("cp.async.cg.shared.global [%0], [%1], 16, %2;\n" :: "r"(dst), "l"(src), "r"(sz));
}
__device__ __forceinline__ void cp_commit() { asm volatile("cp.async.commit_group;\n"); }
__device__ __forceinline__ void cp_wait0()  { asm volatile("cp.async.wait_group 0;\n"); }
__device__ __forceinline__ void cp_wait1()  { asm volatile("cp.async.wait_group 1;\n"); }

// ---------------- batched rounding pass (all weights, one launch) ----------
struct RTab {
    const float* s[8];
    float* d[8];
    int end[8];          // cumulative end, in float4 units
};

__global__ void __launch_bounds__(256) round_all(RTab t, int total4)
{
    int i = blockIdx.x * 256 + threadIdx.x;
    if (i >= total4) return;
    int j = 0;
    while (i >= t.end[j]) j++;
    int off = i - (j ? t.end[j - 1] : 0);
    float4 v = ((const float4*)t.s[j])[off];
    v.x = rnd(v.x); v.y = rnd(v.y); v.z = rnd(v.z); v.w = rnd(v.w);
    ((float4*)t.d[j])[off] = v;
}

// ---------------- rmsnorm (output rounded to tf32) --------------------------
__global__ void __launch_bounds__(256) rmsnorm_kernel(
    const float* __restrict__ x, const float* __restrict__ w, float* __restrict__ y)
{
    int row = blockIdx.x;
    const float* xr = x + (size_t)row * EE;
    float vals[3];
    float s = 0.f;
#pragma unroll
    for (int i = 0; i < 3; i++) {
        vals[i] = xr[threadIdx.x + i * 256];
        s += vals[i] * vals[i];
    }
#pragma unroll
    for (int o = 16; o; o >>= 1) s += __shfl_down_sync(0xffffffffu, s, o);
    __shared__ float red[8];
    if ((threadIdx.x & 31) == 0) red[threadIdx.x >> 5] = s;
    __syncthreads();
    if (threadIdx.x < 8) {
        float t = red[threadIdx.x];
#pragma unroll
        for (int o = 4; o; o >>= 1) t += __shfl_down_sync(0xffu, t, o);
        if (threadIdx.x == 0) red[0] = t;
    }
    __syncthreads();
    float r = rsqrtf(red[0] * (1.0f / EE) + 1.1920929e-7f);
    float* yr = y + (size_t)row * EE;
#pragma unroll
    for (int i = 0; i < 3; i++) {
        int c = threadIdx.x + i * 256;
        yr[c] = rnd(vals[i] * r * w[c]);
    }
}

// ---------------- tf32 GEMM: 128 threads, 4 warps (2x2), 64m x NT/2 n per warp
// C = A @ W^T over K, then optionally + A2 @ B2^T over K2 (dual-K accumulate)
// flags bit0: relu, bit1: round output to tf32
// blockIdx.z==1 selects (Bz,biasz,Cz) alternate problem (same A/M/N/K)
#define ST 36
#define ATILE (128*ST)      // 4608 floats

template<int NT>
__global__ void __launch_bounds__(128, 2) mma_gemm(
    const float* __restrict__ A, const float* __restrict__ B, float* __restrict__ C,
    const float* __restrict__ bias, const float* __restrict__ res,
    const float* __restrict__ inter4, const float* __restrict__ b2,
    const float* __restrict__ A2, const float* __restrict__ B2,
    int K2, int lda2, int ldb2,
    const float* __restrict__ Bz, const float* __restrict__ biasz, float* __restrict__ Cz,
    int M, int N, int K, int lda, int ldb, int ldc, int flags)
{
    constexpr int BTILE = NT * ST;
    constexpr int STG = ATILE + BTILE;
    constexpr int NWT = NT / 16;     // n-subtiles per warp (8, 6 or 4)

    extern __shared__ float dyn[];
    if (blockIdx.z == 1) { B = Bz; bias = biasz; C = Cz; }

    const int tid  = threadIdx.x;
    const int lane = tid & 31, warp = tid >> 5;
    const int g = lane >> 2, t4 = lane & 3;
    const int wm = (warp >> 1) * 64;           // 0 or 64
    const int wn = (warp & 1) * (NT / 2);      // 0 or NT/2
    const int mBase = blockIdx.y * 128, nBase = blockIdx.x * NT;
    const int lr = tid >> 3;            // 0..15
    const int kA = (tid & 7) * 4;       // 0,4,..,28

    const unsigned sb = (unsigned)__cvta_generic_to_shared(dyn);

    const int n1 = K >> 5, n2 = K2 >> 5, nT = n1 + n2;

    float acc[4][NWT][4];
#pragma unroll
    for (int i = 0; i < 4; i++)
#pragma unroll
        for (int j = 0; j < NWT; j++)
#pragma unroll
            for (int c = 0; c < 4; c++) acc[i][j][c] = 0.f;

    auto issue = [&](int t, int buf) {
        const float* Ab; const float* Bb; int la, lb, k0;
        if (t < n1) { Ab = A;  Bb = B;  la = lda;  lb = ldb;  k0 = t * 32; }
        else        { Ab = A2; Bb = B2; la = lda2; lb = ldb2; k0 = (t - n1) * 32; }
#pragma unroll
        for (int r = 0; r < 8; r++) {
            int row = lr + 16 * r;
            const float* ap = Ab + (size_t)(mBase + row) * la + k0 + kA;
            cp16(sb + (buf * STG + row * ST + kA) * 4, ap);
        }
#pragma unroll
        for (int r = 0; r < NT / 16; r++) {
            int row = lr + 16 * r;
            bool ok = (nBase + row) < N;
            const float* bp = ok ? (Bb + (size_t)(nBase + row) * lb + k0 + kA) : Bb;
            cp16z(sb + (buf * STG + ATILE + row * ST + kA) * 4, bp, ok ? 16 : 0);
        }
        cp_commit();
    };

    issue(0, 0);
    if (nT > 1) issue(1, 1);

    for (int t = 0; t < nT; t++) {
        if (t < nT - 1) cp_wait1(); else cp_wait0();
        __syncthreads();
        if (t + 2 < nT) issue(t + 2, (t + 2) % 3);

        const float* As = dyn + (t % 3) * STG;
        const float* Bs = As + ATILE;
#pragma unroll
        for (int kk = 0; kk < 4; kk++) {
            const int kb = kk * 8;
            unsigned a[4][4], b[NWT][2];
#pragma unroll
            for (int mt = 0; mt < 4; mt++) {
                int mr = wm + mt * 16 + g;
                a[mt][0] = __float_as_uint(As[mr * ST + kb + t4]);
                a[mt][1] = __float_as_uint(As[(mr + 8) * ST + kb + t4]);
                a[mt][2] = __float_as_uint(As[mr * ST + kb + t4 + 4]);
                a[mt][3] = __float_as_uint(As[(mr + 8) * ST + kb + t4 + 4]);
            }
#pragma unroll
            for (int nt = 0; nt < NWT; nt++) {
                int nc = wn + nt * 8 + g;
                b[nt][0] = __float_as_uint(Bs[nc * ST + kb + t4]);
                b[nt][1] = __float_as_uint(Bs[nc * ST + kb + t4 + 4]);
            }
#pragma unroll
            for (int mt = 0; mt < 4; mt++)
#pragma unroll
                for (int nt = 0; nt < NWT; nt++)
                    mma_tf32(acc[mt][nt], a[mt], b[nt]);
        }
    }

    const bool relu = flags & 1;
    const bool roundC = flags & 2;
#pragma unroll
    for (int mt = 0; mt < 4; mt++) {
#pragma unroll
        for (int half = 0; half < 2; half++) {
            int m = mBase + wm + mt * 16 + g + half * 8;
            float i0 = 0.f, i1 = 0.f, i2 = 0.f, i3 = 0.f;
            if (inter4) {
                const float* ip = inter4 + (size_t)m * 4;
                i0 = ip[0]; i1 = ip[1]; i2 = ip[2]; i3 = ip[3];
            }
#pragma unroll
            for (int nt = 0; nt < NWT; nt++) {
#pragma unroll
                for (int c = 0; c < 2; c++) {
                    int n = nBase + wn + nt * 8 + 2 * t4 + c;
                    if (n < N) {
                        float v = acc[mt][nt][half * 2 + c];
                        if (bias) v += bias[n];
                        if (res)  v += res[(size_t)m * ldc + n];
                        if (b2) {
                            const float* bp = b2 + (size_t)n * 4;
                            v += i0 * bp[0] + i1 * bp[1] + i2 * bp[2] + i3 * bp[3];
                        }
                        if (relu) v = fmaxf(v, 0.f);
                        if (roundC) v = rnd(v);
                        C[(size_t)m * ldc + n] = v;
                    }
                }
            }
        }
    }
}

// ---------------- flash attention --------------------------------------------
// 128 threads = 4 warps; each warp owns 32 query rows (two 16-row MMA halves)
// sharing the same K/V fragment loads. QK tf32, PV bf16.
#define QP 68
#define VP 72
#define KVST (64*QP + 64*VP)   // 8960 floats per stage
#define FSTAGES 3
__global__ void __launch_bounds__(128, 2) flash_attn(
    const float* __restrict__ qkv, float* __restrict__ ctx)
{
    extern __shared__ float pool[];
    const unsigned sb = (unsigned)__cvta_generic_to_shared(pool);

    const int z = blockIdx.y, b = z / HH, h = z % HH;
    const float* base = qkv + (size_t)b * SS * 3 * EE + h * HD;
    const int q0 = blockIdx.x * 128;
    const int tid = threadIdx.x, lane = tid & 31, warp = tid >> 5;
    const int g = lane >> 2, t4 = lane & 3;
    const float qscale = 0.125f * 1.4426950408889634f;  // 1/sqrt(64) * log2(e)

    // ---- stage Q (scaled, tf32) through smem: 128 rows x 64 cols
#pragma unroll
    for (int r = 0; r < 16; r++) {
        int idx = tid + r * 128;           // 0..2047 float4 slots
        int row = idx >> 4, c4 = (idx & 15) * 4;
        float4 v = *(const float4*)(base + (size_t)(q0 + row) * 3 * EE + c4);
        float4 w;
        w.x = rnd(v.x * qscale);
        w.y = rnd(v.y * qscale);
        w.z = rnd(v.z * qscale);
        w.w = rnd(v.w * qscale);
        *(float4*)(pool + row * QP + c4) = w;
    }
    __syncthreads();
    unsigned qfA[8][4], qfB[8][4];
    const int wq = warp * 32;
#pragma unroll
    for (int kc = 0; kc < 8; kc++) {
        qfA[kc][0] = __float_as_uint(pool[(wq + g)      * QP + kc * 8 + t4]);
        qfA[kc][1] = __float_as_uint(pool[(wq + g + 8)  * QP + kc * 8 + t4]);
        qfA[kc][2] = __float_as_uint(pool[(wq + g)      * QP + kc * 8 + t4 + 4]);
        qfA[kc][3] = __float_as_uint(pool[(wq + g + 8)  * QP + kc * 8 + t4 + 4]);
        qfB[kc][0] = __float_as_uint(pool[(wq + g + 16) * QP + kc * 8 + t4]);
        qfB[kc][1] = __float_as_uint(pool[(wq + g + 24) * QP + kc * 8 + t4]);
        qfB[kc][2] = __float_as_uint(pool[(wq + g + 16) * QP + kc * 8 + t4 + 4]);
        qfB[kc][3] = __float_as_uint(pool[(wq + g + 24) * QP + kc * 8 + t4 + 4]);
    }
    __syncthreads();

    float oA[8][4], oB[8][4];
#pragma unroll
    for (int v = 0; v < 8; v++)
#pragma unroll
        for (int c = 0; c < 4; c++) { oA[v][c] = 0.f; oB[v][c] = 0.f; }
    float lA0 = 0.f, lA1 = 0.f, lB0 = 0.f, lB1 = 0.f;

    const int frow = tid >> 4, fseg = (tid & 15) * 4;   // 8 rows/thread, 16 thr/row

    auto issue_kv = [&](int kt, int buf) {
#pragma unroll
        for (int r = 0; r < 8; r++) {
            int row = frow + r * 8;
            const float* kp = base + EE     + (size_t)(kt * 64 + row) * 3 * EE + fseg;
            const float* vp = base + 2 * EE + (size_t)(kt * 64 + row) * 3 * EE + fseg;
            cp16(sb + (buf * KVST + row * QP + fseg) * 4, kp);
            cp16(sb + (buf * KVST + 64 * QP + row * VP + fseg) * 4, vp);
        }
        cp_commit();
    };

    const int NKT = SS / 64;
    issue_kv(0, 0);
    issue_kv(1, 1);

    for (int kt = 0; kt < NKT; kt++) {
        if (kt < NKT - 1) cp_wait1(); else cp_wait0();
        __syncthreads();
        if (kt + 2 < NKT) issue_kv(kt + 2, (kt + 2) % FSTAGES);

        const float* Ks = pool + (kt % FSTAGES) * KVST;
        const float* Vs = Ks + 64 * QP;

        // ---- scores for both 16-row halves, sharing K fragments
        float sA[8][4], sB[8][4];
#pragma unroll
        for (int j = 0; j < 8; j++)
#pragma unroll
            for (int c = 0; c < 4; c++) { sA[j][c] = 0.f; sB[j][c] = 0.f; }
#pragma unroll
        for (int j = 0; j < 8; j++) {
#pragma unroll
            for (int kc = 0; kc < 8; kc++) {
                unsigned bfr[2];
                bfr[0] = __float_as_uint(Ks[(j * 8 + g) * QP + kc * 8 + t4]);
                bfr[1] = __float_as_uint(Ks[(j * 8 + g) * QP + kc * 8 + t4 + 4]);
                mma_tf32(sA[j], qfA[kc], bfr);
                mma_tf32(sB[j], qfB[kc], bfr);
            }
        }

        // ---- max-free softmax: p = exp2(s) (scores bounded; fp32-safe)
#pragma unroll
        for (int j = 0; j < 8; j++) {
            sA[j][0] = exp2f(sA[j][0]); sA[j][1] = exp2f(sA[j][1]);
            sA[j][2] = exp2f(sA[j][2]); sA[j][3] = exp2f(sA[j][3]);
            lA0 += sA[j][0] + sA[j][1];
            lA1 += sA[j][2] + sA[j][3];
            sB[j][0] = exp2f(sB[j][0]); sB[j][1] = exp2f(sB[j][1]);
            sB[j][2] = exp2f(sB[j][2]); sB[j][3] = exp2f(sB[j][3]);
            lB0 += sB[j][0] + sB[j][1];
            lB1 += sB[j][2] + sB[j][3];
        }

        // ---- P.V in bf16 m16n8k16, sharing V fragments between halves
#pragma unroll
        for (int j2 = 0; j2 < 4; j2++) {
            unsigned paA[4], paB[4];
            paA[0] = packbf(sA[2 * j2][1],     sA[2 * j2][0]);
            paA[1] = packbf(sA[2 * j2][3],     sA[2 * j2][2]);
            paA[2] = packbf(sA[2 * j2 + 1][1], sA[2 * j2 + 1][0]);
            paA[3] = packbf(sA[2 * j2 + 1][3], sA[2 * j2 + 1][2]);
            paB[0] = packbf(sB[2 * j2][1],     sB[2 * j2][0]);
            paB[1] = packbf(sB[2 * j2][3],     sB[2 * j2][2]);
            paB[2] = packbf(sB[2 * j2 + 1][1], sB[2 * j2 + 1][0]);
            paB[3] = packbf(sB[2 * j2 + 1][3], sB[2 * j2 + 1][2]);
            const float* vr0 = Vs + (j2 * 16 + 2 * t4) * VP;
            const float* vr1 = vr0 + VP;
            const float* vr2 = vr0 + 8 * VP;
            const float* vr3 = vr2 + VP;
#pragma unroll
            for (int v = 0; v < 8; v++) {
                int d = v * 8 + g;
                unsigned b0 = packbf(vr1[d], vr0[d]);
                unsigned b1 = packbf(vr3[d], vr2[d]);
                mma_bf16(oA[v], paA, b0, b1);
                mma_bf16(oB[v], paB, b0, b1);
            }
        }
    }

    // ---- finalize (rounded: ctx feeds out_proj GEMM)
    lA0 += __shfl_xor_sync(0xffffffffu, lA0, 1);
    lA0 += __shfl_xor_sync(0xffffffffu, lA0, 2);
    lA1 += __shfl_xor_sync(0xffffffffu, lA1, 1);
    lA1 += __shfl_xor_sync(0xffffffffu, lA1, 2);
    lB0 += __shfl_xor_sync(0xffffffffu, lB0, 1);
    lB0 += __shfl_xor_sync(0xffffffffu, lB0, 2);
    lB1 += __shfl_xor_sync(0xffffffffu, lB1, 1);
    lB1 += __shfl_xor_sync(0xffffffffu, lB1, 2);
    float iA0 = 1.f / lA0, iA1 = 1.f / lA1, iB0 = 1.f / lB0, iB1 = 1.f / lB1;
    int row0 = q0 + wq + g;
    float* c0p = ctx + ((size_t)(b * SS + row0))      * EE + h * HD;
    float* c1p = ctx + ((size_t)(b * SS + row0 + 8))  * EE + h * HD;
    float* c2p = ctx + ((size_t)(b * SS + row0 + 16)) * EE + h * HD;
    float* c3p = ctx + ((size_t)(b * SS + row0 + 24)) * EE + h * HD;
#pragma unroll
    for (int v = 0; v < 8; v++) {
        int col = v * 8 + 2 * t4;
        *(float2*)(c0p + col) = make_float2(rnd(oA[v][0] * iA0), rnd(oA[v][1] * iA0));
        *(float2*)(c1p + col) = make_float2(rnd(oA[v][2] * iA1), rnd(oA[v][3] * iA1));
        *(float2*)(c2p + col) = make_float2(rnd(oB[v][0] * iB0), rnd(oB[v][1] * iB0));
        *(float2*)(c3p + col) = make_float2(rnd(oB[v][2] * iB1), rnd(oB[v][3] * iB1));
    }
}

// ---------------- small helper kernels -------------------------------------
__global__ void build_WBt(const float* __restrict__ hB_w2,
                          const float* __restrict__ hB_b2,
                          float* __restrict__ WBt)
{
    int idx = blockIdx.x * 256 + threadIdx.x;
    if (idx >= (RR * HID + RR) * EE) return;
    int n = idx / EE, e = idx % EE;
    float val;
    if (n < RR * HID) {
        int r = n >> 7, h = n & 127;
        val = hB_w2[((size_t)(r * EE + e)) * HID + h];
    } else {
        val = hB_b2[(n - RR * HID) * EE + e];
    }
    WBt[idx] = rnd(val);
}

__global__ void __launch_bounds__(256) interu_kernel(
    const float* __restrict__ v, const float* __restrict__ hB,
    const float* __restrict__ hA, float* __restrict__ inter, float* __restrict__ u)
{
    int wtok = (blockIdx.x * 256 + threadIdx.x) >> 5;
    int lane = threadIdx.x & 31;
    if (wtok >= MM) return;
    const float* vr = v + (size_t)wtok * (RR * HID + RR);
    const float* br = hB + (size_t)wtok * HID;
    float hb[4], ha[4];
#pragma unroll
    for (int j = 0; j < 4; j++) {
        hb[j] = br[lane + j * 32];
        ha[j] = hA[(size_t)wtok * HID + lane + j * 32];
    }
    float iv[RR];
#pragma unroll
    for (int r = 0; r < RR; r++) {
        float s = 0.f;
#pragma unroll
        for (int j = 0; j < 4; j++) s += hb[j] * vr[r * HID + lane + j * 32];
#pragma unroll
        for (int o = 16; o; o >>= 1) s += __shfl_xor_sync(0xffffffffu, s, o);
        iv[r] = s + vr[RR * HID + r];
    }
    if (lane < RR) inter[wtok * RR + lane] = iv[lane];
    float* ur = u + (size_t)wtok * RR * HID;
#pragma unroll
    for (int r = 0; r < RR; r++)
#pragma unroll
        for (int j = 0; j < 4; j++)
            ur[r * HID + lane + j * 32] = rnd(iv[r] * ha[j]);
}

// ---------------- launch ----------------------------------------------------
extern "C" void kernel_launch(void* const* d_in, const int* in_sizes, int n_in,
                              void* d_out, int out_size)
{
    const float* src       = (const float*)d_in[0];
    const float* task      = (const float*)d_in[1];
    const float* norm1_w   = (const float*)d_in[2];
    const float* norm2_w   = (const float*)d_in[3];
    const float* in_proj_w = (const float*)d_in[4];
    const float* out_proj_w= (const float*)d_in[5];
    const float* ffn1_w    = (const float*)d_in[6];
    const float* ffn1_b    = (const float*)d_in[7];
    const float* ffn2_w    = (const float*)d_in[8];
    const float* ffn2_b    = (const float*)d_in[9];
    const float* hA_w1     = (const float*)d_in[10];
    const float* hA_b1     = (const float*)d_in[11];
    const float* hA_w2     = (const float*)d_in[12];
    const float* hA_b2     = (const float*)d_in[13];
    const float* hB_w1     = (const float*)d_in[14];
    const float* hB_b1     = (const float*)d_in[15];
    const float* hB_w2     = (const float*)d_in[16];
    const float* hB_b2     = (const float*)d_in[17];
    float* out = (float*)d_out;

    float *x1, *qkv, *ctx, *src2, *x2, *hA, *hB, *WBt, *v, *inter, *u, *hbuf;
    float *r_task, *r_inproj, *r_outproj, *r_ffn1, *r_ffn2, *r_hAw2, *r_hw1;
    cudaGetSymbolAddress((void**)&x1,   g_x1);
    cudaGetSymbolAddress((void**)&qkv,  g_qkv);
    cudaGetSymbolAddress((void**)&ctx,  g_ctx);
    cudaGetSymbolAddress((void**)&src2, g_src2);
    cudaGetSymbolAddress((void**)&x2,   g_x2);
    cudaGetSymbolAddress((void**)&hA,   g_hA);
    cudaGetSymbolAddress((void**)&hB,   g_hB);
    cudaGetSymbolAddress((void**)&WBt,  g_WBt);
    cudaGetSymbolAddress((void**)&v,    g_v);
    cudaGetSymbolAddress((void**)&inter,g_int);
    cudaGetSymbolAddress((void**)&u,    g_u);
    cudaGetSymbolAddress((void**)&hbuf, g_h);
    cudaGetSymbolAddress((void**)&r_task,   g_r_task);
    cudaGetSymbolAddress((void**)&r_inproj, g_r_inproj);
    cudaGetSymbolAddress((void**)&r_outproj,g_r_outproj);
    cudaGetSymbolAddress((void**)&r_ffn1,   g_r_ffn1);
    cudaGetSymbolAddress((void**)&r_ffn2,   g_r_ffn2);
    cudaGetSymbolAddress((void**)&r_hAw2,   g_r_hAw2);
    cudaGetSymbolAddress((void**)&r_hw1,    g_r_hw1);

    const int DS128 = 3 * (ATILE + 128 * ST) * 4;   // 110592 B
    const int DS96  = 3 * (ATILE + 96 * ST) * 4;    //  96768 B
    const int DS64  = 3 * (ATILE + 64 * ST) * 4;    //  82944 B
    const int FS = FSTAGES * KVST * 4;              // 107520 B
    cudaFuncSetAttribute(mma_gemm<128>, cudaFuncAttributeMaxDynamicSharedMemorySize, DS128);
    cudaFuncSetAttribute(mma_gemm<96>,  cudaFuncAttributeMaxDynamicSharedMemorySize, DS96);
    cudaFuncSetAttribute(mma_gemm<64>,  cudaFuncAttributeMaxDynamicSharedMemorySize, DS64);
    cudaFuncSetAttribute(flash_attn,    cudaFuncAttributeMaxDynamicSharedMemorySize, FS);

    // 0) pre-round all GEMM operands to tf32 (one launch)
    {
        RTab t;
        const float* ss[8] = {task, in_proj_w, out_proj_w, ffn1_w, ffn2_w, hA_w2, hA_w1, hB_w1};
        float* dd[8] = {r_task, r_inproj, r_outproj, r_ffn1, r_ffn2, r_hAw2, r_hw1, r_hw1 + HID * TT};
        int nn[8] = {MM * TT / 4, 3 * EE * EE / 4, EE * EE / 4, FF * EE / 4,
                     EE * FF / 4, FF * RR * HID / 4, HID * TT / 4, HID * TT / 4};
        int cum = 0;
        for (int j = 0; j < 8; j++) { t.s[j] = ss[j]; t.d[j] = dd[j]; cum += nn[j]; t.end[j] = cum; }
        round_all<<<(cum + 255) / 256, 256>>>(t, cum);
    }

    // 1) x1 = rmsnorm(src, norm1_w) (rounded)
    rmsnorm_kernel<<<MM, 256>>>(src, norm1_w, x1);

    // 2) qkv = x1 @ in_proj^T (rounded out)
    mma_gemm<128><<<dim3(18, 32, 1), 128, DS128>>>(
        x1, r_inproj, qkv, nullptr, nullptr, nullptr, nullptr,
        nullptr, nullptr, 0, 0, 0, nullptr, nullptr, nullptr,
        MM, 3 * EE, EE, EE, EE, 3 * EE, 2);

    // 3) flash attention -> ctx (rounded); 128 threads, 4 warps x 32 q-rows
    flash_attn<<<dim3(SS / 128, BB * HH), 128, FS>>>(qkv, ctx);

    // 4) src2 = src + ctx @ out_proj^T  (N=768, NT=96 -> 256 CTAs = 1 wave)
    mma_gemm<96><<<dim3(8, 32, 1), 128, DS96>>>(
        ctx, r_outproj, src2, nullptr, src, nullptr, nullptr,
        nullptr, nullptr, 0, 0, 0, nullptr, nullptr, nullptr,
        MM, EE, EE, EE, EE, EE, 0);

    // 5) x2 = rmsnorm(src2) (rounded)
    rmsnorm_kernel<<<MM, 256>>>(src2, norm2_w, x2);

    // 6) hypernet hiddens hA & hB in one launch (z selects problem; NT=64 -> 128 CTAs)
    mma_gemm<64><<<dim3(2, 32, 2), 128, DS64>>>(
        r_task, r_hw1, hA, hA_b1, nullptr, nullptr, nullptr,
        nullptr, nullptr, 0, 0, 0,
        r_hw1 + HID * TT, hB_b1, hB,
        MM, HID, TT, TT, TT, HID, 1);

    // 7) rearranged B-side weights (rounded)
    build_WBt<<<((RR * HID + RR) * EE + 255) / 256, 256>>>(hB_w2, hB_b2, WBt);

    // 8) v = x2 @ WBt^T  [4096, 516]  (NT=64 -> 288 CTAs)
    mma_gemm<64><<<dim3(9, 32, 1), 128, DS64>>>(
        x2, WBt, v, nullptr, nullptr, nullptr, nullptr,
        nullptr, nullptr, 0, 0, 0, nullptr, nullptr, nullptr,
        MM, RR * HID + RR, EE, EE, EE, RR * HID + RR, 0);

    // 9) inter + u (rounded)
    interu_kernel<<<MM / 8, 256>>>(v, hB, hA, inter, u);

    // 10) fused FFN1 + LoRA expand: hbuf = relu(x2@ffn1^T + u@hAw2^T + ffn1_b + lora_b), rounded
    mma_gemm<128><<<dim3(24, 32, 1), 128, DS128>>>(
        x2, r_ffn1, hbuf, ffn1_b, nullptr, inter, hA_b2,
        u, r_hAw2, RR * HID, RR * HID, RR * HID,
        nullptr, nullptr, nullptr,
        MM, FF, EE, EE, EE, FF, 3);

    // 11) out = src2 + hbuf @ ffn2^T + ffn2_b  (N=768, NT=96 -> 256 CTAs = 1 wave)
    mma_gemm<96><<<dim3(8, 32, 1), 128, DS96>>>(
        hbuf, r_ffn2, out, ffn2_b, src2, nullptr, nullptr,
        nullptr, nullptr, 0, 0, 0, nullptr, nullptr, nullptr,
        MM, EE, FF, FF, FF, EE, 0);
}

// round 15
// speedup vs baseline: 1.0425x; 1.0046x over previous
#include <cuda_runtime.h>
#include <cuda_bf16.h>
#include <math.h>
#include <stdint.h>

// Problem constants
#define BB 2
#define SS 2048
#define EE 768
#define FF 3072
#define RR 4
#define TT 128
#define HH 12
#define HD 64
#define HID 128
#define MM (BB*SS)          // 4096 tokens

// ---------------- scratch (device globals; no cudaMalloc allowed) ----------
__device__ float g_x1  [MM*EE];
__device__ float g_qkv [MM*3*EE];
__device__ float g_ctx [MM*EE];
__device__ float g_src2[MM*EE];
__device__ float g_x2  [MM*EE];
__device__ float g_hA  [MM*HID];
__device__ float g_hB  [MM*HID];
__device__ float g_WBt [(RR*HID+RR)*EE];
__device__ float g_v   [MM*(RR*HID+RR)];
__device__ float g_int [MM*RR];
__device__ float g_u   [MM*RR*HID];
__device__ float g_h   [MM*FF];
// rounded copies of GEMM operands
__device__ float g_r_task  [MM*TT];
__device__ float g_r_inproj[3*EE*EE];
__device__ float g_r_outproj[EE*EE];
__device__ float g_r_ffn1  [FF*EE];
__device__ float g_r_ffn2  [EE*FF];
__device__ float g_r_hAw2  [FF*RR*HID];
__device__ float g_r_hw1   [2*HID*TT];

// ---------------- helpers ---------------------------------------------------
__device__ __forceinline__ unsigned f2tf32(float f) {
    unsigned u;
    asm("cvt.rna.tf32.f32 %0, %1;" : "=r"(u) : "f"(f));
    return u;
}
__device__ __forceinline__ float rnd(float f) { return __uint_as_float(f2tf32(f)); }

__device__ __forceinline__ unsigned packbf(float hi, float lo) {
    unsigned r;
    asm("cvt.rn.bf16x2.f32 %0, %1, %2;" : "=r"(r) : "f"(hi), "f"(lo));
    return r;
}

__device__ __forceinline__ void mma_tf32(float c[4], const unsigned a[4], const unsigned b[2]) {
    asm volatile(
        "mma.sync.aligned.m16n8k8.row.col.f32.tf32.tf32.f32 "
        "{%0,%1,%2,%3}, {%4,%5,%6,%7}, {%8,%9}, {%0,%1,%2,%3};\n"
        : "+f"(c[0]), "+f"(c[1]), "+f"(c[2]), "+f"(c[3])
        : "r"(a[0]), "r"(a[1]), "r"(a[2]), "r"(a[3]), "r"(b[0]), "r"(b[1]));
}

__device__ __forceinline__ void mma_bf16(float c[4], const unsigned a[4], unsigned b0, unsigned b1) {
    asm volatile(
        "mma.sync.aligned.m16n8k16.row.col.f32.bf16.bf16.f32 "
        "{%0,%1,%2,%3}, {%4,%5,%6,%7}, {%8,%9}, {%0,%1,%2,%3};\n"
        : "+f"(c[0]), "+f"(c[1]), "+f"(c[2]), "+f"(c[3])
        : "r"(a[0]), "r"(a[1]), "r"(a[2]), "r"(a[3]), "r"(b0), "r"(b1));
}

__device__ __forceinline__ void cp16(unsigned dst, const float* src) {
    asm volatile("cp.async.cg.shared.global [%0], [%1], 16;\n" :: "r"(dst), "l"(src));
}
__device__ __forceinline__ void cp16z(unsigned dst, const float* src, int sz) {
    asm volatile("cp.async.cg.shared.global [%0], [%1], 16, %2;\n" :: "r"(dst), "l"(src), "r"(sz));
}
__device__ __forceinline__ void cp_commit() { asm volatile("cp.async.commit_group;\n"); }
__device__ __forceinline__ void cp_wait0()  { asm volatile("cp.async.wait_group 0;\n"); }
__device__ __forceinline__ void cp_wait1()  { asm volatile("cp.async.wait_group 1;\n"); }

// ---------------- batched rounding pass (all weights, one launch) ----------
struct RTab {
    const float* s[8];
    float* d[8];
    int end[8];          // cumulative end, in float4 units
};

__global__ void __launch_bounds__(256) round_all(RTab t, int total4)
{
    int i = blockIdx.x * 256 + threadIdx.x;
    if (i >= total4) return;
    int j = 0;
    while (i >= t.end[j]) j++;
    int off = i - (j ? t.end[j - 1] : 0);
    float4 v = ((const float4*)t.s[j])[off];
    v.x = rnd(v.x); v.y = rnd(v.y); v.z = rnd(v.z); v.w = rnd(v.w);
    ((float4*)t.d[j])[off] = v;
}

// ---------------- rmsnorm (output rounded to tf32) --------------------------
__global__ void __launch_bounds__(256) rmsnorm_kernel(
    const float* __restrict__ x, const float* __restrict__ w, float* __restrict__ y)
{
    int row = blockIdx.x;
    const float* xr = x + (size_t)row * EE;
    float vals[3];
    float s = 0.f;
#pragma unroll
    for (int i = 0; i < 3; i++) {
        vals[i] = xr[threadIdx.x + i * 256];
        s += vals[i] * vals[i];
    }
#pragma unroll
    for (int o = 16; o; o >>= 1) s += __shfl_down_sync(0xffffffffu, s, o);
    __shared__ float red[8];
    if ((threadIdx.x & 31) == 0) red[threadIdx.x >> 5] = s;
    __syncthreads();
    if (threadIdx.x < 8) {
        float t = red[threadIdx.x];
#pragma unroll
        for (int o = 4; o; o >>= 1) t += __shfl_down_sync(0xffu, t, o);
        if (threadIdx.x == 0) red[0] = t;
    }
    __syncthreads();
    float r = rsqrtf(red[0] * (1.0f / EE) + 1.1920929e-7f);
    float* yr = y + (size_t)row * EE;
#pragma unroll
    for (int i = 0; i < 3; i++) {
        int c = threadIdx.x + i * 256;
        yr[c] = rnd(vals[i] * r * w[c]);
    }
}

// ---------------- tf32 GEMM: persistent CTAs over linearized tiles ----------
// 128 threads, 4 warps (2x2), 64m x NT/2 n per warp.
// C = A @ W^T over K, then optionally + A2 @ B2^T over K2 (dual-K accumulate)
// flags bit0: relu, bit1: round output to tf32
// blockIdx.z==1 selects (Bz,biasz,Cz) alternate problem (same A/M/N/K)
// tile tb in [0,tilesTot): bx = tb % tilesX, by = tb / tilesX
#define ST 36
#define ATILE (128*ST)      // 4608 floats

template<int NT>
__global__ void __launch_bounds__(128, 2) mma_gemm(
    const float* __restrict__ A, const float* __restrict__ B, float* __restrict__ C,
    const float* __restrict__ bias, const float* __restrict__ res,
    const float* __restrict__ inter4, const float* __restrict__ b2,
    const float* __restrict__ A2, const float* __restrict__ B2,
    int K2, int lda2, int ldb2,
    const float* __restrict__ Bz, const float* __restrict__ biasz, float* __restrict__ Cz,
    int tilesX, int tilesTot,
    int M, int N, int K, int lda, int ldb, int ldc, int flags)
{
    constexpr int BTILE = NT * ST;
    constexpr int STG = ATILE + BTILE;
    constexpr int NWT = NT / 16;     // n-subtiles per warp (8, 6 or 4)

    extern __shared__ float dyn[];
    if (blockIdx.z == 1) { B = Bz; bias = biasz; C = Cz; }

    const int tid  = threadIdx.x;
    const int lane = tid & 31, warp = tid >> 5;
    const int g = lane >> 2, t4 = lane & 3;
    const int wm = (warp >> 1) * 64;           // 0 or 64
    const int wn = (warp & 1) * (NT / 2);      // 0 or NT/2
    const int lr = tid >> 3;            // 0..15
    const int kA = (tid & 7) * 4;       // 0,4,..,28

    const unsigned sb = (unsigned)__cvta_generic_to_shared(dyn);

    const int n1 = K >> 5, n2 = K2 >> 5, nT = n1 + n2;
    const bool relu = flags & 1;
    const bool roundC = flags & 2;

    int mBase, nBase;

    auto issue = [&](int t, int buf) {
        const float* Ab; const float* Bb; int la, lb, k0;
        if (t < n1) { Ab = A;  Bb = B;  la = lda;  lb = ldb;  k0 = t * 32; }
        else        { Ab = A2; Bb = B2; la = lda2; lb = ldb2; k0 = (t - n1) * 32; }
#pragma unroll
        for (int r = 0; r < 8; r++) {
            int row = lr + 16 * r;
            const float* ap = Ab + (size_t)(mBase + row) * la + k0 + kA;
            cp16(sb + (buf * STG + row * ST + kA) * 4, ap);
        }
#pragma unroll
        for (int r = 0; r < NT / 16; r++) {
            int row = lr + 16 * r;
            bool ok = (nBase + row) < N;
            const float* bp = ok ? (Bb + (size_t)(nBase + row) * lb + k0 + kA) : Bb;
            cp16z(sb + (buf * STG + ATILE + row * ST + kA) * 4, bp, ok ? 16 : 0);
        }
        cp_commit();
    };

    for (int tb = blockIdx.x; tb < tilesTot; tb += gridDim.x) {
        const int bx = tb % tilesX, by = tb / tilesX;
        mBase = by * 128;
        nBase = bx * NT;

        float acc[4][NWT][4];
#pragma unroll
        for (int i = 0; i < 4; i++)
#pragma unroll
            for (int j = 0; j < NWT; j++)
#pragma unroll
                for (int c = 0; c < 4; c++) acc[i][j][c] = 0.f;

        issue(0, 0);
        if (nT > 1) issue(1, 1);

        for (int t = 0; t < nT; t++) {
            if (t < nT - 1) cp_wait1(); else cp_wait0();
            __syncthreads();
            if (t + 2 < nT) issue(t + 2, (t + 2) % 3);

            const float* As = dyn + (t % 3) * STG;
            const float* Bs = As + ATILE;
#pragma unroll
            for (int kk = 0; kk < 4; kk++) {
                const int kb = kk * 8;
                unsigned a[4][4], b[NWT][2];
#pragma unroll
                for (int mt = 0; mt < 4; mt++) {
                    int mr = wm + mt * 16 + g;
                    a[mt][0] = __float_as_uint(As[mr * ST + kb + t4]);
                    a[mt][1] = __float_as_uint(As[(mr + 8) * ST + kb + t4]);
                    a[mt][2] = __float_as_uint(As[mr * ST + kb + t4 + 4]);
                    a[mt][3] = __float_as_uint(As[(mr + 8) * ST + kb + t4 + 4]);
                }
#pragma unroll
                for (int nt = 0; nt < NWT; nt++) {
                    int nc = wn + nt * 8 + g;
                    b[nt][0] = __float_as_uint(Bs[nc * ST + kb + t4]);
                    b[nt][1] = __float_as_uint(Bs[nc * ST + kb + t4 + 4]);
                }
#pragma unroll
                for (int mt = 0; mt < 4; mt++)
#pragma unroll
                    for (int nt = 0; nt < NWT; nt++)
                        mma_tf32(acc[mt][nt], a[mt], b[nt]);
            }
        }

#pragma unroll
        for (int mt = 0; mt < 4; mt++) {
#pragma unroll
            for (int half = 0; half < 2; half++) {
                int m = mBase + wm + mt * 16 + g + half * 8;
                float i0 = 0.f, i1 = 0.f, i2 = 0.f, i3 = 0.f;
                if (inter4) {
                    const float* ip = inter4 + (size_t)m * 4;
                    i0 = ip[0]; i1 = ip[1]; i2 = ip[2]; i3 = ip[3];
                }
#pragma unroll
                for (int nt = 0; nt < NWT; nt++) {
#pragma unroll
                    for (int c = 0; c < 2; c++) {
                        int n = nBase + wn + nt * 8 + 2 * t4 + c;
                        if (n < N) {
                            float v = acc[mt][nt][half * 2 + c];
                            if (bias) v += bias[n];
                            if (res)  v += res[(size_t)m * ldc + n];
                            if (b2) {
                                const float* bp = b2 + (size_t)n * 4;
                                v += i0 * bp[0] + i1 * bp[1] + i2 * bp[2] + i3 * bp[3];
                            }
                            if (relu) v = fmaxf(v, 0.f);
                            if (roundC) v = rnd(v);
                            C[(size_t)m * ldc + n] = v;
                        }
                    }
                }
            }
        }
        __syncthreads();   // all warps done with smem before next tile's prologue
    }
}

// ---------------- flash attention --------------------------------------------
// 128 threads = 4 warps; each warp owns 32 query rows (two 16-row MMA halves)
// sharing the same K/V fragment loads. QK tf32, PV bf16.
#define QP 68
#define VP 72
#define KVST (64*QP + 64*VP)   // 8960 floats per stage
#define FSTAGES 3
__global__ void __launch_bounds__(128, 2) flash_attn(
    const float* __restrict__ qkv, float* __restrict__ ctx)
{
    extern __shared__ float pool[];
    const unsigned sb = (unsigned)__cvta_generic_to_shared(pool);

    const int z = blockIdx.y, b = z / HH, h = z % HH;
    const float* base = qkv + (size_t)b * SS * 3 * EE + h * HD;
    const int q0 = blockIdx.x * 128;
    const int tid = threadIdx.x, lane = tid & 31, warp = tid >> 5;
    const int g = lane >> 2, t4 = lane & 3;
    const float qscale = 0.125f * 1.4426950408889634f;  // 1/sqrt(64) * log2(e)

    // ---- stage Q (scaled, tf32) through smem: 128 rows x 64 cols
#pragma unroll
    for (int r = 0; r < 16; r++) {
        int idx = tid + r * 128;           // 0..2047 float4 slots
        int row = idx >> 4, c4 = (idx & 15) * 4;
        float4 v = *(const float4*)(base + (size_t)(q0 + row) * 3 * EE + c4);
        float4 w;
        w.x = rnd(v.x * qscale);
        w.y = rnd(v.y * qscale);
        w.z = rnd(v.z * qscale);
        w.w = rnd(v.w * qscale);
        *(float4*)(pool + row * QP + c4) = w;
    }
    __syncthreads();
    unsigned qfA[8][4], qfB[8][4];
    const int wq = warp * 32;
#pragma unroll
    for (int kc = 0; kc < 8; kc++) {
        qfA[kc][0] = __float_as_uint(pool[(wq + g)      * QP + kc * 8 + t4]);
        qfA[kc][1] = __float_as_uint(pool[(wq + g + 8)  * QP + kc * 8 + t4]);
        qfA[kc][2] = __float_as_uint(pool[(wq + g)      * QP + kc * 8 + t4 + 4]);
        qfA[kc][3] = __float_as_uint(pool[(wq + g + 8)  * QP + kc * 8 + t4 + 4]);
        qfB[kc][0] = __float_as_uint(pool[(wq + g + 16) * QP + kc * 8 + t4]);
        qfB[kc][1] = __float_as_uint(pool[(wq + g + 24) * QP + kc * 8 + t4]);
        qfB[kc][2] = __float_as_uint(pool[(wq + g + 16) * QP + kc * 8 + t4 + 4]);
        qfB[kc][3] = __float_as_uint(pool[(wq + g + 24) * QP + kc * 8 + t4 + 4]);
    }
    __syncthreads();

    float oA[8][4], oB[8][4];
#pragma unroll
    for (int v = 0; v < 8; v++)
#pragma unroll
        for (int c = 0; c < 4; c++) { oA[v][c] = 0.f; oB[v][c] = 0.f; }
    float lA0 = 0.f, lA1 = 0.f, lB0 = 0.f, lB1 = 0.f;

    const int frow = tid >> 4, fseg = (tid & 15) * 4;   // 8 rows/thread, 16 thr/row

    auto issue_kv = [&](int kt, int buf) {
#pragma unroll
        for (int r = 0; r < 8; r++) {
            int row = frow + r * 8;
            const float* kp = base + EE     + (size_t)(kt * 64 + row) * 3 * EE + fseg;
            const float* vp = base + 2 * EE + (size_t)(kt * 64 + row) * 3 * EE + fseg;
            cp16(sb + (buf * KVST + row * QP + fseg) * 4, kp);
            cp16(sb + (buf * KVST + 64 * QP + row * VP + fseg) * 4, vp);
        }
        cp_commit();
    };

    const int NKT = SS / 64;
    issue_kv(0, 0);
    issue_kv(1, 1);

    for (int kt = 0; kt < NKT; kt++) {
        if (kt < NKT - 1) cp_wait1(); else cp_wait0();
        __syncthreads();
        if (kt + 2 < NKT) issue_kv(kt + 2, (kt + 2) % FSTAGES);

        const float* Ks = pool + (kt % FSTAGES) * KVST;
        const float* Vs = Ks + 64 * QP;

        // ---- scores for both 16-row halves, sharing K fragments
        float sA[8][4], sB[8][4];
#pragma unroll
        for (int j = 0; j < 8; j++)
#pragma unroll
            for (int c = 0; c < 4; c++) { sA[j][c] = 0.f; sB[j][c] = 0.f; }
#pragma unroll
        for (int j = 0; j < 8; j++) {
#pragma unroll
            for (int kc = 0; kc < 8; kc++) {
                unsigned bfr[2];
                bfr[0] = __float_as_uint(Ks[(j * 8 + g) * QP + kc * 8 + t4]);
                bfr[1] = __float_as_uint(Ks[(j * 8 + g) * QP + kc * 8 + t4 + 4]);
                mma_tf32(sA[j], qfA[kc], bfr);
                mma_tf32(sB[j], qfB[kc], bfr);
            }
        }

        // ---- max-free softmax: p = exp2(s) (scores bounded; fp32-safe)
#pragma unroll
        for (int j = 0; j < 8; j++) {
            sA[j][0] = exp2f(sA[j][0]); sA[j][1] = exp2f(sA[j][1]);
            sA[j][2] = exp2f(sA[j][2]); sA[j][3] = exp2f(sA[j][3]);
            lA0 += sA[j][0] + sA[j][1];
            lA1 += sA[j][2] + sA[j][3];
            sB[j][0] = exp2f(sB[j][0]); sB[j][1] = exp2f(sB[j][1]);
            sB[j][2] = exp2f(sB[j][2]); sB[j][3] = exp2f(sB[j][3]);
            lB0 += sB[j][0] + sB[j][1];
            lB1 += sB[j][2] + sB[j][3];
        }

        // ---- P.V in bf16 m16n8k16, sharing V fragments between halves
#pragma unroll
        for (int j2 = 0; j2 < 4; j2++) {
            unsigned paA[4], paB[4];
            paA[0] = packbf(sA[2 * j2][1],     sA[2 * j2][0]);
            paA[1] = packbf(sA[2 * j2][3],     sA[2 * j2][2]);
            paA[2] = packbf(sA[2 * j2 + 1][1], sA[2 * j2 + 1][0]);
            paA[3] = packbf(sA[2 * j2 + 1][3], sA[2 * j2 + 1][2]);
            paB[0] = packbf(sB[2 * j2][1],     sB[2 * j2][0]);
            paB[1] = packbf(sB[2 * j2][3],     sB[2 * j2][2]);
            paB[2] = packbf(sB[2 * j2 + 1][1], sB[2 * j2 + 1][0]);
            paB[3] = packbf(sB[2 * j2 + 1][3], sB[2 * j2 + 1][2]);
            const float* vr0 = Vs + (j2 * 16 + 2 * t4) * VP;
            const float* vr1 = vr0 + VP;
            const float* vr2 = vr0 + 8 * VP;
            const float* vr3 = vr2 + VP;
#pragma unroll
            for (int v = 0; v < 8; v++) {
                int d = v * 8 + g;
                unsigned b0 = packbf(vr1[d], vr0[d]);
                unsigned b1 = packbf(vr3[d], vr2[d]);
                mma_bf16(oA[v], paA, b0, b1);
                mma_bf16(oB[v], paB, b0, b1);
            }
        }
    }

    // ---- finalize (rounded: ctx feeds out_proj GEMM)
    lA0 += __shfl_xor_sync(0xffffffffu, lA0, 1);
    lA0 += __shfl_xor_sync(0xffffffffu, lA0, 2);
    lA1 += __shfl_xor_sync(0xffffffffu, lA1, 1);
    lA1 += __shfl_xor_sync(0xffffffffu, lA1, 2);
    lB0 += __shfl_xor_sync(0xffffffffu, lB0, 1);
    lB0 += __shfl_xor_sync(0xffffffffu, lB0, 2);
    lB1 += __shfl_xor_sync(0xffffffffu, lB1, 1);
    lB1 += __shfl_xor_sync(0xffffffffu, lB1, 2);
    float iA0 = 1.f / lA0, iA1 = 1.f / lA1, iB0 = 1.f / lB0, iB1 = 1.f / lB1;
    int row0 = q0 + wq + g;
    float* c0p = ctx + ((size_t)(b * SS + row0))      * EE + h * HD;
    float* c1p = ctx + ((size_t)(b * SS + row0 + 8))  * EE + h * HD;
    float* c2p = ctx + ((size_t)(b * SS + row0 + 16)) * EE + h * HD;
    float* c3p = ctx + ((size_t)(b * SS + row0 + 24)) * EE + h * HD;
#pragma unroll
    for (int v = 0; v < 8; v++) {
        int col = v * 8 + 2 * t4;
        *(float2*)(c0p + col) = make_float2(rnd(oA[v][0] * iA0), rnd(oA[v][1] * iA0));
        *(float2*)(c1p + col) = make_float2(rnd(oA[v][2] * iA1), rnd(oA[v][3] * iA1));
        *(float2*)(c2p + col) = make_float2(rnd(oB[v][0] * iB0), rnd(oB[v][1] * iB0));
        *(float2*)(c3p + col) = make_float2(rnd(oB[v][2] * iB1), rnd(oB[v][3] * iB1));
    }
}

// ---------------- small helper kernels -------------------------------------
__global__ void build_WBt(const float* __restrict__ hB_w2,
                          const float* __restrict__ hB_b2,
                          float* __restrict__ WBt)
{
    int idx = blockIdx.x * 256 + threadIdx.x;
    if (idx >= (RR * HID + RR) * EE) return;
    int n = idx / EE, e = idx % EE;
    float val;
    if (n < RR * HID) {
        int r = n >> 7, h = n & 127;
        val = hB_w2[((size_t)(r * EE + e)) * HID + h];
    } else {
        val = hB_b2[(n - RR * HID) * EE + e];
    }
    WBt[idx] = rnd(val);
}

__global__ void __launch_bounds__(256) interu_kernel(
    const float* __restrict__ v, const float* __restrict__ hB,
    const float* __restrict__ hA, float* __restrict__ inter, float* __restrict__ u)
{
    int wtok = (blockIdx.x * 256 + threadIdx.x) >> 5;
    int lane = threadIdx.x & 31;
    if (wtok >= MM) return;
    const float* vr = v + (size_t)wtok * (RR * HID + RR);
    const float* br = hB + (size_t)wtok * HID;
    float hb[4], ha[4];
#pragma unroll
    for (int j = 0; j < 4; j++) {
        hb[j] = br[lane + j * 32];
        ha[j] = hA[(size_t)wtok * HID + lane + j * 32];
    }
    float iv[RR];
#pragma unroll
    for (int r = 0; r < RR; r++) {
        float s = 0.f;
#pragma unroll
        for (int j = 0; j < 4; j++) s += hb[j] * vr[r * HID + lane + j * 32];
#pragma unroll
        for (int o = 16; o; o >>= 1) s += __shfl_xor_sync(0xffffffffu, s, o);
        iv[r] = s + vr[RR * HID + r];
    }
    if (lane < RR) inter[wtok * RR + lane] = iv[lane];
    float* ur = u + (size_t)wtok * RR * HID;
#pragma unroll
    for (int r = 0; r < RR; r++)
#pragma unroll
        for (int j = 0; j < 4; j++)
            ur[r * HID + lane + j * 32] = rnd(iv[r] * ha[j]);
}

// ---------------- launch ----------------------------------------------------
extern "C" void kernel_launch(void* const* d_in, const int* in_sizes, int n_in,
                              void* d_out, int out_size)
{
    const float* src       = (const float*)d_in[0];
    const float* task      = (const float*)d_in[1];
    const float* norm1_w   = (const float*)d_in[2];
    const float* norm2_w   = (const float*)d_in[3];
    const float* in_proj_w = (const float*)d_in[4];
    const float* out_proj_w= (const float*)d_in[5];
    const float* ffn1_w    = (const float*)d_in[6];
    const float* ffn1_b    = (const float*)d_in[7];
    const float* ffn2_w    = (const float*)d_in[8];
    const float* ffn2_b    = (const float*)d_in[9];
    const float* hA_w1     = (const float*)d_in[10];
    const float* hA_b1     = (const float*)d_in[11];
    const float* hA_w2     = (const float*)d_in[12];
    const float* hA_b2     = (const float*)d_in[13];
    const float* hB_w1     = (const float*)d_in[14];
    const float* hB_b1     = (const float*)d_in[15];
    const float* hB_w2     = (const float*)d_in[16];
    const float* hB_b2     = (const float*)d_in[17];
    float* out = (float*)d_out;

    float *x1, *qkv, *ctx, *src2, *x2, *hA, *hB, *WBt, *v, *inter, *u, *hbuf;
    float *r_task, *r_inproj, *r_outproj, *r_ffn1, *r_ffn2, *r_hAw2, *r_hw1;
    cudaGetSymbolAddress((void**)&x1,   g_x1);
    cudaGetSymbolAddress((void**)&qkv,  g_qkv);
    cudaGetSymbolAddress((void**)&ctx,  g_ctx);
    cudaGetSymbolAddress((void**)&src2, g_src2);
    cudaGetSymbolAddress((void**)&x2,   g_x2);
    cudaGetSymbolAddress((void**)&hA,   g_hA);
    cudaGetSymbolAddress((void**)&hB,   g_hB);
    cudaGetSymbolAddress((void**)&WBt,  g_WBt);
    cudaGetSymbolAddress((void**)&v,    g_v);
    cudaGetSymbolAddress((void**)&inter,g_int);
    cudaGetSymbolAddress((void**)&u,    g_u);
    cudaGetSymbolAddress((void**)&hbuf, g_h);
    cudaGetSymbolAddress((void**)&r_task,   g_r_task);
    cudaGetSymbolAddress((void**)&r_inproj, g_r_inproj);
    cudaGetSymbolAddress((void**)&r_outproj,g_r_outproj);
    cudaGetSymbolAddress((void**)&r_ffn1,   g_r_ffn1);
    cudaGetSymbolAddress((void**)&r_ffn2,   g_r_ffn2);
    cudaGetSymbolAddress((void**)&r_hAw2,   g_r_hAw2);
    cudaGetSymbolAddress((void**)&r_hw1,    g_r_hw1);

    const int DS128 = 3 * (ATILE + 128 * ST) * 4;   // 110592 B
    const int DS96  = 3 * (ATILE + 96 * ST) * 4;    //  96768 B
    const int DS64  = 3 * (ATILE + 64 * ST) * 4;    //  82944 B
    const int FS = FSTAGES * KVST * 4;              // 107520 B
    cudaFuncSetAttribute(mma_gemm<128>, cudaFuncAttributeMaxDynamicSharedMemorySize, DS128);
    cudaFuncSetAttribute(mma_gemm<96>,  cudaFuncAttributeMaxDynamicSharedMemorySize, DS96);
    cudaFuncSetAttribute(mma_gemm<64>,  cudaFuncAttributeMaxDynamicSharedMemorySize, DS64);
    cudaFuncSetAttribute(flash_attn,    cudaFuncAttributeMaxDynamicSharedMemorySize, FS);

    // 0) pre-round all GEMM operands to tf32 (one launch)
    {
        RTab t;
        const float* ss[8] = {task, in_proj_w, out_proj_w, ffn1_w, ffn2_w, hA_w2, hA_w1, hB_w1};
        float* dd[8] = {r_task, r_inproj, r_outproj, r_ffn1, r_ffn2, r_hAw2, r_hw1, r_hw1 + HID * TT};
        int nn[8] = {MM * TT / 4, 3 * EE * EE / 4, EE * EE / 4, FF * EE / 4,
                     EE * FF / 4, FF * RR * HID / 4, HID * TT / 4, HID * TT / 4};
        int cum = 0;
        for (int j = 0; j < 8; j++) { t.s[j] = ss[j]; t.d[j] = dd[j]; cum += nn[j]; t.end[j] = cum; }
        round_all<<<(cum + 255) / 256, 256>>>(t, cum);
    }

    // 1) x1 = rmsnorm(src, norm1_w) (rounded)
    rmsnorm_kernel<<<MM, 256>>>(src, norm1_w, x1);

    // 2) qkv = x1 @ in_proj^T (persistent: 576 tiles on 296 CTAs)
    mma_gemm<128><<<dim3(296, 1, 1), 128, DS128>>>(
        x1, r_inproj, qkv, nullptr, nullptr, nullptr, nullptr,
        nullptr, nullptr, 0, 0, 0, nullptr, nullptr, nullptr,
        18, 576,
        MM, 3 * EE, EE, EE, EE, 3 * EE, 2);

    // 3) flash attention -> ctx (rounded); 128 threads, 4 warps x 32 q-rows
    flash_attn<<<dim3(SS / 128, BB * HH), 128, FS>>>(qkv, ctx);

    // 4) src2 = src + ctx @ out_proj^T  (N=768, NT=96 -> 256 CTAs = 1 wave)
    mma_gemm<96><<<dim3(256, 1, 1), 128, DS96>>>(
        ctx, r_outproj, src2, nullptr, src, nullptr, nullptr,
        nullptr, nullptr, 0, 0, 0, nullptr, nullptr, nullptr,
        8, 256,
        MM, EE, EE, EE, EE, EE, 0);

    // 5) x2 = rmsnorm(src2) (rounded)
    rmsnorm_kernel<<<MM, 256>>>(src2, norm2_w, x2);

    // 6) hypernet hiddens hA & hB in one launch (z selects problem)
    mma_gemm<64><<<dim3(64, 1, 2), 128, DS64>>>(
        r_task, r_hw1, hA, hA_b1, nullptr, nullptr, nullptr,
        nullptr, nullptr, 0, 0, 0,
        r_hw1 + HID * TT, hB_b1, hB,
        2, 64,
        MM, HID, TT, TT, TT, HID, 1);

    // 7) rearranged B-side weights (rounded)
    build_WBt<<<((RR * HID + RR) * EE + 255) / 256, 256>>>(hB_w2, hB_b2, WBt);

    // 8) v = x2 @ WBt^T  [4096, 516]  (288 CTAs ~ 1 wave)
    mma_gemm<64><<<dim3(288, 1, 1), 128, DS64>>>(
        x2, WBt, v, nullptr, nullptr, nullptr, nullptr,
        nullptr, nullptr, 0, 0, 0, nullptr, nullptr, nullptr,
        9, 288,
        MM, RR * HID + RR, EE, EE, EE, RR * HID + RR, 0);

    // 9) inter + u (rounded)
    interu_kernel<<<MM / 8, 256>>>(v, hB, hA, inter, u);

    // 10) fused FFN1 + LoRA expand (persistent: 768 tiles on 296 CTAs)
    mma_gemm<128><<<dim3(296, 1, 1), 128, DS128>>>(
        x2, r_ffn1, hbuf, ffn1_b, nullptr, inter, hA_b2,
        u, r_hAw2, RR * HID, RR * HID, RR * HID,
        nullptr, nullptr, nullptr,
        24, 768,
        MM, FF, EE, EE, EE, FF, 3);

    // 11) out = src2 + hbuf @ ffn2^T + ffn2_b  (N=768, NT=96 -> 256 CTAs = 1 wave)
    mma_gemm<96><<<dim3(256, 1, 1), 128, DS96>>>(
        hbuf, r_ffn2, out, ffn2_b, src2, nullptr, nullptr,
        nullptr, nullptr, 0, 0, 0, nullptr, nullptr, nullptr,
        8, 256,
        MM, EE, FF, FF, FF, EE, 0);
}

// round 16
// speedup vs baseline: 1.0455x; 1.0029x over previous
#include <cuda_runtime.h>
#include <cuda_bf16.h>
#include <math.h>
#include <stdint.h>

// Problem constants
#define BB 2
#define SS 2048
#define EE 768
#define FF 3072
#define RR 4
#define TT 128
#define HH 12
#define HD 64
#define HID 128
#define MM (BB*SS)          // 4096 tokens

// ---------------- scratch (device globals; no cudaMalloc allowed) ----------
__device__ float g_x1  [MM*EE];
__device__ float g_qkv [MM*3*EE];
__device__ float g_ctx [MM*EE];
__device__ float g_src2[MM*EE];
__device__ float g_x2  [MM*EE];
__device__ float g_hA  [MM*HID];
__device__ float g_hB  [MM*HID];
__device__ float g_WBt [(RR*HID+RR)*EE];
__device__ float g_v   [MM*(RR*HID+RR)];
__device__ float g_int [MM*RR];
__device__ float g_u   [MM*RR*HID];
__device__ float g_h   [MM*FF];
// rounded copies of GEMM operands
__device__ float g_r_task  [MM*TT];
__device__ float g_r_inproj[3*EE*EE];
__device__ float g_r_outproj[EE*EE];
__device__ float g_r_ffn1  [FF*EE];
__device__ float g_r_ffn2  [EE*FF];
__device__ float g_r_hAw2  [FF*RR*HID];
__device__ float g_r_hw1   [2*HID*TT];

// ---------------- helpers ---------------------------------------------------
__device__ __forceinline__ unsigned f2tf32(float f) {
    unsigned u;
    asm("cvt.rna.tf32.f32 %0, %1;" : "=r"(u) : "f"(f));
    return u;
}
__device__ __forceinline__ float rnd(float f) { return __uint_as_float(f2tf32(f)); }

__device__ __forceinline__ unsigned packbf(float hi, float lo) {
    unsigned r;
    asm("cvt.rn.bf16x2.f32 %0, %1, %2;" : "=r"(r) : "f"(hi), "f"(lo));
    return r;
}

__device__ __forceinline__ void mma_tf32(float c[4], const unsigned a[4], const unsigned b[2]) {
    asm volatile(
        "mma.sync.aligned.m16n8k8.row.col.f32.tf32.tf32.f32 "
        "{%0,%1,%2,%3}, {%4,%5,%6,%7}, {%8,%9}, {%0,%1,%2,%3};\n"
        : "+f"(c[0]), "+f"(c[1]), "+f"(c[2]), "+f"(c[3])
        : "r"(a[0]), "r"(a[1]), "r"(a[2]), "r"(a[3]), "r"(b[0]), "r"(b[1]));
}

__device__ __forceinline__ void mma_bf16(float c[4], const unsigned a[4], unsigned b0, unsigned b1) {
    asm volatile(
        "mma.sync.aligned.m16n8k16.row.col.f32.bf16.bf16.f32 "
        "{%0,%1,%2,%3}, {%4,%5,%6,%7}, {%8,%9}, {%0,%1,%2,%3};\n"
        : "+f"(c[0]), "+f"(c[1]), "+f"(c[2]), "+f"(c[3])
        : "r"(a[0]), "r"(a[1]), "r"(a[2]), "r"(a[3]), "r"(b0), "r"(b1));
}

__device__ __forceinline__ void cp16(unsigned dst, const float* src) {
    asm volatile("cp.async.cg.shared.global [%0], [%1], 16;\n" :: "r"(dst), "l"(src));
}
__device__ __forceinline__ void cp16z(unsigned dst, const float* src, int sz) {
    asm volatile("cp.async.cg.shared.global [%0], [%1], 16, %2;\n" :: "r"(dst), "l"(src), "r"(sz));
}
__device__ __forceinline__ void cp_commit() { asm volatile("cp.async.commit_group;\n"); }
__device__ __forceinline__ void cp_wait0()  { asm volatile("cp.async.wait_group 0;\n"); }
__device__ __forceinline__ void cp_wait1()  { asm volatile("cp.async.wait_group 1;\n"); }

// ---------------- batched rounding pass (all weights, one launch) ----------
struct RTab {
    const float* s[8];
    float* d[8];
    int end[8];          // cumulative end, in float4 units
};

__global__ void __launch_bounds__(256) round_all(RTab t, int total4)
{
    int i = blockIdx.x * 256 + threadIdx.x;
    if (i >= total4) return;
    int j = 0;
    while (i >= t.end[j]) j++;
    int off = i - (j ? t.end[j - 1] : 0);
    float4 v = ((const float4*)t.s[j])[off];
    v.x = rnd(v.x); v.y = rnd(v.y); v.z = rnd(v.z); v.w = rnd(v.w);
    ((float4*)t.d[j])[off] = v;
}

// ---------------- rmsnorm (output rounded to tf32) --------------------------
__global__ void __launch_bounds__(256) rmsnorm_kernel(
    const float* __restrict__ x, const float* __restrict__ w, float* __restrict__ y)
{
    int row = blockIdx.x;
    const float* xr = x + (size_t)row * EE;
    float vals[3];
    float s = 0.f;
#pragma unroll
    for (int i = 0; i < 3; i++) {
        vals[i] = xr[threadIdx.x + i * 256];
        s += vals[i] * vals[i];
    }
#pragma unroll
    for (int o = 16; o; o >>= 1) s += __shfl_down_sync(0xffffffffu, s, o);
    __shared__ float red[8];
    if ((threadIdx.x & 31) == 0) red[threadIdx.x >> 5] = s;
    __syncthreads();
    if (threadIdx.x < 8) {
        float t = red[threadIdx.x];
#pragma unroll
        for (int o = 4; o; o >>= 1) t += __shfl_down_sync(0xffu, t, o);
        if (threadIdx.x == 0) red[0] = t;
    }
    __syncthreads();
    float r = rsqrtf(red[0] * (1.0f / EE) + 1.1920929e-7f);
    float* yr = y + (size_t)row * EE;
#pragma unroll
    for (int i = 0; i < 3; i++) {
        int c = threadIdx.x + i * 256;
        yr[c] = rnd(vals[i] * r * w[c]);
    }
}

// ---------------- tf32 GEMM: persistent, NT=96, 2-stage, 3 CTAs/SM ----------
// 128 threads, 4 warps (2x2), 64m x 48n per warp.
// C = A @ W^T over K, then optionally + A2 @ B2^T over K2 (dual-K accumulate)
// flags bit0: relu, bit1: round output to tf32
// blockIdx.z==1 selects (Bz,biasz,Cz) alternate problem (same A/M/N/K)
#define ST 36
#define ATILE (128*ST)      // 4608 floats

template<int NT>
__global__ void __launch_bounds__(128, 3) mma_gemm(
    const float* __restrict__ A, const float* __restrict__ B, float* __restrict__ C,
    const float* __restrict__ bias, const float* __restrict__ res,
    const float* __restrict__ inter4, const float* __restrict__ b2,
    const float* __restrict__ A2, const float* __restrict__ B2,
    int K2, int lda2, int ldb2,
    const float* __restrict__ Bz, const float* __restrict__ biasz, float* __restrict__ Cz,
    int tilesX, int tilesTot,
    int M, int N, int K, int lda, int ldb, int ldc, int flags)
{
    constexpr int BTILE = NT * ST;
    constexpr int STG = ATILE + BTILE;
    constexpr int NWT = NT / 16;     // 6 for NT=96

    extern __shared__ float dyn[];
    if (blockIdx.z == 1) { B = Bz; bias = biasz; C = Cz; }

    const int tid  = threadIdx.x;
    const int lane = tid & 31, warp = tid >> 5;
    const int g = lane >> 2, t4 = lane & 3;
    const int wm = (warp >> 1) * 64;           // 0 or 64
    const int wn = (warp & 1) * (NT / 2);      // 0 or NT/2
    const int lr = tid >> 3;            // 0..15
    const int kA = (tid & 7) * 4;       // 0,4,..,28

    const unsigned sb = (unsigned)__cvta_generic_to_shared(dyn);

    const int n1 = K >> 5, n2 = K2 >> 5, nT = n1 + n2;
    const bool relu = flags & 1;
    const bool roundC = flags & 2;

    int mBase, nBase;

    auto issue = [&](int t, int buf) {
        const float* Ab; const float* Bb; int la, lb, k0;
        if (t < n1) { Ab = A;  Bb = B;  la = lda;  lb = ldb;  k0 = t * 32; }
        else        { Ab = A2; Bb = B2; la = lda2; lb = ldb2; k0 = (t - n1) * 32; }
#pragma unroll
        for (int r = 0; r < 8; r++) {
            int row = lr + 16 * r;
            const float* ap = Ab + (size_t)(mBase + row) * la + k0 + kA;
            cp16(sb + (buf * STG + row * ST + kA) * 4, ap);
        }
#pragma unroll
        for (int r = 0; r < NT / 16; r++) {
            int row = lr + 16 * r;
            bool ok = (nBase + row) < N;
            const float* bp = ok ? (Bb + (size_t)(nBase + row) * lb + k0 + kA) : Bb;
            cp16z(sb + (buf * STG + ATILE + row * ST + kA) * 4, bp, ok ? 16 : 0);
        }
        cp_commit();
    };

    for (int tb = blockIdx.x; tb < tilesTot; tb += gridDim.x) {
        const int bx = tb % tilesX, by = tb / tilesX;
        mBase = by * 128;
        nBase = bx * NT;

        float acc[4][NWT][4];
#pragma unroll
        for (int i = 0; i < 4; i++)
#pragma unroll
            for (int j = 0; j < NWT; j++)
#pragma unroll
                for (int c = 0; c < 4; c++) acc[i][j][c] = 0.f;

        issue(0, 0);
        if (nT > 1) issue(1, 1);

        for (int t = 0; t < nT; t++) {
            if (t < nT - 1) cp_wait1(); else cp_wait0();
            __syncthreads();

            const float* As = dyn + (t & 1) * STG;
            const float* Bs = As + ATILE;
#pragma unroll
            for (int kk = 0; kk < 4; kk++) {
                const int kb = kk * 8;
                unsigned a[4][4], b[NWT][2];
#pragma unroll
                for (int mt = 0; mt < 4; mt++) {
                    int mr = wm + mt * 16 + g;
                    a[mt][0] = __float_as_uint(As[mr * ST + kb + t4]);
                    a[mt][1] = __float_as_uint(As[(mr + 8) * ST + kb + t4]);
                    a[mt][2] = __float_as_uint(As[mr * ST + kb + t4 + 4]);
                    a[mt][3] = __float_as_uint(As[(mr + 8) * ST + kb + t4 + 4]);
                }
#pragma unroll
                for (int nt = 0; nt < NWT; nt++) {
                    int nc = wn + nt * 8 + g;
                    b[nt][0] = __float_as_uint(Bs[nc * ST + kb + t4]);
                    b[nt][1] = __float_as_uint(Bs[nc * ST + kb + t4 + 4]);
                }
#pragma unroll
                for (int mt = 0; mt < 4; mt++)
#pragma unroll
                    for (int nt = 0; nt < NWT; nt++)
                        mma_tf32(acc[mt][nt], a[mt], b[nt]);
            }
            __syncthreads();
            if (t + 2 < nT) issue(t + 2, t & 1);
        }

#pragma unroll
        for (int mt = 0; mt < 4; mt++) {
#pragma unroll
            for (int half = 0; half < 2; half++) {
                int m = mBase + wm + mt * 16 + g + half * 8;
                float i0 = 0.f, i1 = 0.f, i2 = 0.f, i3 = 0.f;
                if (inter4) {
                    const float* ip = inter4 + (size_t)m * 4;
                    i0 = ip[0]; i1 = ip[1]; i2 = ip[2]; i3 = ip[3];
                }
#pragma unroll
                for (int nt = 0; nt < NWT; nt++) {
#pragma unroll
                    for (int c = 0; c < 2; c++) {
                        int n = nBase + wn + nt * 8 + 2 * t4 + c;
                        if (n < N) {
                            float v = acc[mt][nt][half * 2 + c];
                            if (bias) v += bias[n];
                            if (res)  v += res[(size_t)m * ldc + n];
                            if (b2) {
                                const float* bp = b2 + (size_t)n * 4;
                                v += i0 * bp[0] + i1 * bp[1] + i2 * bp[2] + i3 * bp[3];
                            }
                            if (relu) v = fmaxf(v, 0.f);
                            if (roundC) v = rnd(v);
                            C[(size_t)m * ldc + n] = v;
                        }
                    }
                }
            }
        }
    }
}

// ---------------- flash attention --------------------------------------------
// 128 threads = 4 warps; each warp owns 32 query rows (two 16-row MMA halves)
// sharing the same K/V fragment loads. QK tf32, PV bf16.
#define QP 68
#define VP 72
#define KVST (64*QP + 64*VP)   // 8960 floats per stage
#define FSTAGES 3
__global__ void __launch_bounds__(128, 2) flash_attn(
    const float* __restrict__ qkv, float* __restrict__ ctx)
{
    extern __shared__ float pool[];
    const unsigned sb = (unsigned)__cvta_generic_to_shared(pool);

    const int z = blockIdx.y, b = z / HH, h = z % HH;
    const float* base = qkv + (size_t)b * SS * 3 * EE + h * HD;
    const int q0 = blockIdx.x * 128;
    const int tid = threadIdx.x, lane = tid & 31, warp = tid >> 5;
    const int g = lane >> 2, t4 = lane & 3;
    const float qscale = 0.125f * 1.4426950408889634f;  // 1/sqrt(64) * log2(e)

    // ---- stage Q (scaled, tf32) through smem: 128 rows x 64 cols
#pragma unroll
    for (int r = 0; r < 16; r++) {
        int idx = tid + r * 128;           // 0..2047 float4 slots
        int row = idx >> 4, c4 = (idx & 15) * 4;
        float4 v = *(const float4*)(base + (size_t)(q0 + row) * 3 * EE + c4);
        float4 w;
        w.x = rnd(v.x * qscale);
        w.y = rnd(v.y * qscale);
        w.z = rnd(v.z * qscale);
        w.w = rnd(v.w * qscale);
        *(float4*)(pool + row * QP + c4) = w;
    }
    __syncthreads();
    unsigned qfA[8][4], qfB[8][4];
    const int wq = warp * 32;
#pragma unroll
    for (int kc = 0; kc < 8; kc++) {
        qfA[kc][0] = __float_as_uint(pool[(wq + g)      * QP + kc * 8 + t4]);
        qfA[kc][1] = __float_as_uint(pool[(wq + g + 8)  * QP + kc * 8 + t4]);
        qfA[kc][2] = __float_as_uint(pool[(wq + g)      * QP + kc * 8 + t4 + 4]);
        qfA[kc][3] = __float_as_uint(pool[(wq + g + 8)  * QP + kc * 8 + t4 + 4]);
        qfB[kc][0] = __float_as_uint(pool[(wq + g + 16) * QP + kc * 8 + t4]);
        qfB[kc][1] = __float_as_uint(pool[(wq + g + 24) * QP + kc * 8 + t4]);
        qfB[kc][2] = __float_as_uint(pool[(wq + g + 16) * QP + kc * 8 + t4 + 4]);
        qfB[kc][3] = __float_as_uint(pool[(wq + g + 24) * QP + kc * 8 + t4 + 4]);
    }
    __syncthreads();

    float oA[8][4], oB[8][4];
#pragma unroll
    for (int v = 0; v < 8; v++)
#pragma unroll
        for (int c = 0; c < 4; c++) { oA[v][c] = 0.f; oB[v][c] = 0.f; }
    float lA0 = 0.f, lA1 = 0.f, lB0 = 0.f, lB1 = 0.f;

    const int frow = tid >> 4, fseg = (tid & 15) * 4;   // 8 rows/thread, 16 thr/row

    auto issue_kv = [&](int kt, int buf) {
#pragma unroll
        for (int r = 0; r < 8; r++) {
            int row = frow + r * 8;
            const float* kp = base + EE     + (size_t)(kt * 64 + row) * 3 * EE + fseg;
            const float* vp = base + 2 * EE + (size_t)(kt * 64 + row) * 3 * EE + fseg;
            cp16(sb + (buf * KVST + row * QP + fseg) * 4, kp);
            cp16(sb + (buf * KVST + 64 * QP + row * VP + fseg) * 4, vp);
        }
        cp_commit();
    };

    const int NKT = SS / 64;
    issue_kv(0, 0);
    issue_kv(1, 1);

    for (int kt = 0; kt < NKT; kt++) {
        if (kt < NKT - 1) cp_wait1(); else cp_wait0();
        __syncthreads();
        if (kt + 2 < NKT) issue_kv(kt + 2, (kt + 2) % FSTAGES);

        const float* Ks = pool + (kt % FSTAGES) * KVST;
        const float* Vs = Ks + 64 * QP;

        // ---- scores for both 16-row halves, sharing K fragments
        float sA[8][4], sB[8][4];
#pragma unroll
        for (int j = 0; j < 8; j++)
#pragma unroll
            for (int c = 0; c < 4; c++) { sA[j][c] = 0.f; sB[j][c] = 0.f; }
#pragma unroll
        for (int j = 0; j < 8; j++) {
#pragma unroll
            for (int kc = 0; kc < 8; kc++) {
                unsigned bfr[2];
                bfr[0] = __float_as_uint(Ks[(j * 8 + g) * QP + kc * 8 + t4]);
                bfr[1] = __float_as_uint(Ks[(j * 8 + g) * QP + kc * 8 + t4 + 4]);
                mma_tf32(sA[j], qfA[kc], bfr);
                mma_tf32(sB[j], qfB[kc], bfr);
            }
        }

        // ---- max-free softmax: p = exp2(s) (scores bounded; fp32-safe)
#pragma unroll
        for (int j = 0; j < 8; j++) {
            sA[j][0] = exp2f(sA[j][0]); sA[j][1] = exp2f(sA[j][1]);
            sA[j][2] = exp2f(sA[j][2]); sA[j][3] = exp2f(sA[j][3]);
            lA0 += sA[j][0] + sA[j][1];
            lA1 += sA[j][2] + sA[j][3];
            sB[j][0] = exp2f(sB[j][0]); sB[j][1] = exp2f(sB[j][1]);
            sB[j][2] = exp2f(sB[j][2]); sB[j][3] = exp2f(sB[j][3]);
            lB0 += sB[j][0] + sB[j][1];
            lB1 += sB[j][2] + sB[j][3];
        }

        // ---- P.V in bf16 m16n8k16, sharing V fragments between halves
#pragma unroll
        for (int j2 = 0; j2 < 4; j2++) {
            unsigned paA[4], paB[4];
            paA[0] = packbf(sA[2 * j2][1],     sA[2 * j2][0]);
            paA[1] = packbf(sA[2 * j2][3],     sA[2 * j2][2]);
            paA[2] = packbf(sA[2 * j2 + 1][1], sA[2 * j2 + 1][0]);
            paA[3] = packbf(sA[2 * j2 + 1][3], sA[2 * j2 + 1][2]);
            paB[0] = packbf(sB[2 * j2][1],     sB[2 * j2][0]);
            paB[1] = packbf(sB[2 * j2][3],     sB[2 * j2][2]);
            paB[2] = packbf(sB[2 * j2 + 1][1], sB[2 * j2 + 1][0]);
            paB[3] = packbf(sB[2 * j2 + 1][3], sB[2 * j2 + 1][2]);
            const float* vr0 = Vs + (j2 * 16 + 2 * t4) * VP;
            const float* vr1 = vr0 + VP;
            const float* vr2 = vr0 + 8 * VP;
            const float* vr3 = vr2 + VP;
#pragma unroll
            for (int v = 0; v < 8; v++) {
                int d = v * 8 + g;
                unsigned b0 = packbf(vr1[d], vr0[d]);
                unsigned b1 = packbf(vr3[d], vr2[d]);
                mma_bf16(oA[v], paA, b0, b1);
                mma_bf16(oB[v], paB, b0, b1);
            }
        }
    }

    // ---- finalize (rounded: ctx feeds out_proj GEMM)
    lA0 += __shfl_xor_sync(0xffffffffu, lA0, 1);
    lA0 += __shfl_xor_sync(0xffffffffu, lA0, 2);
    lA1 += __shfl_xor_sync(0xffffffffu, lA1, 1);
    lA1 += __shfl_xor_sync(0xffffffffu, lA1, 2);
    lB0 += __shfl_xor_sync(0xffffffffu, lB0, 1);
    lB0 += __shfl_xor_sync(0xffffffffu, lB0, 2);
    lB1 += __shfl_xor_sync(0xffffffffu, lB1, 1);
    lB1 += __shfl_xor_sync(0xffffffffu, lB1, 2);
    float iA0 = 1.f / lA0, iA1 = 1.f / lA1, iB0 = 1.f / lB0, iB1 = 1.f / lB1;
    int row0 = q0 + wq + g;
    float* c0p = ctx + ((size_t)(b * SS + row0))      * EE + h * HD;
    float* c1p = ctx + ((size_t)(b * SS + row0 + 8))  * EE + h * HD;
    float* c2p = ctx + ((size_t)(b * SS + row0 + 16)) * EE + h * HD;
    float* c3p = ctx + ((size_t)(b * SS + row0 + 24)) * EE + h * HD;
#pragma unroll
    for (int v = 0; v < 8; v++) {
        int col = v * 8 + 2 * t4;
        *(float2*)(c0p + col) = make_float2(rnd(oA[v][0] * iA0), rnd(oA[v][1] * iA0));
        *(float2*)(c1p + col) = make_float2(rnd(oA[v][2] * iA1), rnd(oA[v][3] * iA1));
        *(float2*)(c2p + col) = make_float2(rnd(oB[v][0] * iB0), rnd(oB[v][1] * iB0));
        *(float2*)(c3p + col) = make_float2(rnd(oB[v][2] * iB1), rnd(oB[v][3] * iB1));
    }
}

// ---------------- small helper kernels -------------------------------------
__global__ void build_WBt(const float* __restrict__ hB_w2,
                          const float* __restrict__ hB_b2,
                          float* __restrict__ WBt)
{
    int idx = blockIdx.x * 256 + threadIdx.x;
    if (idx >= (RR * HID + RR) * EE) return;
    int n = idx / EE, e = idx % EE;
    float val;
    if (n < RR * HID) {
        int r = n >> 7, h = n & 127;
        val = hB_w2[((size_t)(r * EE + e)) * HID + h];
    } else {
        val = hB_b2[(n - RR * HID) * EE + e];
    }
    WBt[idx] = rnd(val);
}

__global__ void __launch_bounds__(256) interu_kernel(
    const float* __restrict__ v, const float* __restrict__ hB,
    const float* __restrict__ hA, float* __restrict__ inter, float* __restrict__ u)
{
    int wtok = (blockIdx.x * 256 + threadIdx.x) >> 5;
    int lane = threadIdx.x & 31;
    if (wtok >= MM) return;
    const float* vr = v + (size_t)wtok * (RR * HID + RR);
    const float* br = hB + (size_t)wtok * HID;
    float hb[4], ha[4];
#pragma unroll
    for (int j = 0; j < 4; j++) {
        hb[j] = br[lane + j * 32];
        ha[j] = hA[(size_t)wtok * HID + lane + j * 32];
    }
    float iv[RR];
#pragma unroll
    for (int r = 0; r < RR; r++) {
        float s = 0.f;
#pragma unroll
        for (int j = 0; j < 4; j++) s += hb[j] * vr[r * HID + lane + j * 32];
#pragma unroll
        for (int o = 16; o; o >>= 1) s += __shfl_xor_sync(0xffffffffu, s, o);
        iv[r] = s + vr[RR * HID + r];
    }
    if (lane < RR) inter[wtok * RR + lane] = iv[lane];
    float* ur = u + (size_t)wtok * RR * HID;
#pragma unroll
    for (int r = 0; r < RR; r++)
#pragma unroll
        for (int j = 0; j < 4; j++)
            ur[r * HID + lane + j * 32] = rnd(iv[r] * ha[j]);
}

// ---------------- launch ----------------------------------------------------
extern "C" void kernel_launch(void* const* d_in, const int* in_sizes, int n_in,
                              void* d_out, int out_size)
{
    const float* src       = (const float*)d_in[0];
    const float* task      = (const float*)d_in[1];
    const float* norm1_w   = (const float*)d_in[2];
    const float* norm2_w   = (const float*)d_in[3];
    const float* in_proj_w = (const float*)d_in[4];
    const float* out_proj_w= (const float*)d_in[5];
    const float* ffn1_w    = (const float*)d_in[6];
    const float* ffn1_b    = (const float*)d_in[7];
    const float* ffn2_w    = (const float*)d_in[8];
    const float* ffn2_b    = (const float*)d_in[9];
    const float* hA_w1     = (const float*)d_in[10];
    const float* hA_b1     = (const float*)d_in[11];
    const float* hA_w2     = (const float*)d_in[12];
    const float* hA_b2     = (const float*)d_in[13];
    const float* hB_w1     = (const float*)d_in[14];
    const float* hB_b1     = (const float*)d_in[15];
    const float* hB_w2     = (const float*)d_in[16];
    const float* hB_b2     = (const float*)d_in[17];
    float* out = (float*)d_out;

    float *x1, *qkv, *ctx, *src2, *x2, *hA, *hB, *WBt, *v, *inter, *u, *hbuf;
    float *r_task, *r_inproj, *r_outproj, *r_ffn1, *r_ffn2, *r_hAw2, *r_hw1;
    cudaGetSymbolAddress((void**)&x1,   g_x1);
    cudaGetSymbolAddress((void**)&qkv,  g_qkv);
    cudaGetSymbolAddress((void**)&ctx,  g_ctx);
    cudaGetSymbolAddress((void**)&src2, g_src2);
    cudaGetSymbolAddress((void**)&x2,   g_x2);
    cudaGetSymbolAddress((void**)&hA,   g_hA);
    cudaGetSymbolAddress((void**)&hB,   g_hB);
    cudaGetSymbolAddress((void**)&WBt,  g_WBt);
    cudaGetSymbolAddress((void**)&v,    g_v);
    cudaGetSymbolAddress((void**)&inter,g_int);
    cudaGetSymbolAddress((void**)&u,    g_u);
    cudaGetSymbolAddress((void**)&hbuf, g_h);
    cudaGetSymbolAddress((void**)&r_task,   g_r_task);
    cudaGetSymbolAddress((void**)&r_inproj, g_r_inproj);
    cudaGetSymbolAddress((void**)&r_outproj,g_r_outproj);
    cudaGetSymbolAddress((void**)&r_ffn1,   g_r_ffn1);
    cudaGetSymbolAddress((void**)&r_ffn2,   g_r_ffn2);
    cudaGetSymbolAddress((void**)&r_hAw2,   g_r_hAw2);
    cudaGetSymbolAddress((void**)&r_hw1,    g_r_hw1);

    const int DS96 = 2 * (ATILE + 96 * ST) * 4;     // 64512 B (2-stage)
    const int FS = FSTAGES * KVST * 4;              // 107520 B
    cudaFuncSetAttribute(mma_gemm<96>, cudaFuncAttributeMaxDynamicSharedMemorySize, DS96);
    cudaFuncSetAttribute(flash_attn,   cudaFuncAttributeMaxDynamicSharedMemorySize, FS);

    const int PG = 444;   // 3 CTAs/SM x 148 SMs

    // 0) pre-round all GEMM operands to tf32 (one launch)
    {
        RTab t;
        const float* ss[8] = {task, in_proj_w, out_proj_w, ffn1_w, ffn2_w, hA_w2, hA_w1, hB_w1};
        float* dd[8] = {r_task, r_inproj, r_outproj, r_ffn1, r_ffn2, r_hAw2, r_hw1, r_hw1 + HID * TT};
        int nn[8] = {MM * TT / 4, 3 * EE * EE / 4, EE * EE / 4, FF * EE / 4,
                     EE * FF / 4, FF * RR * HID / 4, HID * TT / 4, HID * TT / 4};
        int cum = 0;
        for (int j = 0; j < 8; j++) { t.s[j] = ss[j]; t.d[j] = dd[j]; cum += nn[j]; t.end[j] = cum; }
        round_all<<<(cum + 255) / 256, 256>>>(t, cum);
    }

    // 1) x1 = rmsnorm(src, norm1_w) (rounded)
    rmsnorm_kernel<<<MM, 256>>>(src, norm1_w, x1);

    // 2) qkv = x1 @ in_proj^T (768 tiles, persistent on 444 CTAs)
    mma_gemm<96><<<dim3(PG, 1, 1), 128, DS96>>>(
        x1, r_inproj, qkv, nullptr, nullptr, nullptr, nullptr,
        nullptr, nullptr, 0, 0, 0, nullptr, nullptr, nullptr,
        24, 768,
        MM, 3 * EE, EE, EE, EE, 3 * EE, 2);

    // 3) flash attention -> ctx (rounded); 128 threads, 4 warps x 32 q-rows
    flash_attn<<<dim3(SS / 128, BB * HH), 128, FS>>>(qkv, ctx);

    // 4) src2 = src + ctx @ out_proj^T  (256 tiles)
    mma_gemm<96><<<dim3(256, 1, 1), 128, DS96>>>(
        ctx, r_outproj, src2, nullptr, src, nullptr, nullptr,
        nullptr, nullptr, 0, 0, 0, nullptr, nullptr, nullptr,
        8, 256,
        MM, EE, EE, EE, EE, EE, 0);

    // 5) x2 = rmsnorm(src2) (rounded)
    rmsnorm_kernel<<<MM, 256>>>(src2, norm2_w, x2);

    // 6) hypernet hiddens hA & hB in one launch (z selects problem; 64 tiles each)
    mma_gemm<96><<<dim3(64, 1, 2), 128, DS96>>>(
        r_task, r_hw1, hA, hA_b1, nullptr, nullptr, nullptr,
        nullptr, nullptr, 0, 0, 0,
        r_hw1 + HID * TT, hB_b1, hB,
        2, 64,
        MM, HID, TT, TT, TT, HID, 1);

    // 7) rearranged B-side weights (rounded)
    build_WBt<<<((RR * HID + RR) * EE + 255) / 256, 256>>>(hB_w2, hB_b2, WBt);

    // 8) v = x2 @ WBt^T  [4096, 516]  (192 tiles)
    mma_gemm<96><<<dim3(192, 1, 1), 128, DS96>>>(
        x2, WBt, v, nullptr, nullptr, nullptr, nullptr,
        nullptr, nullptr, 0, 0, 0, nullptr, nullptr, nullptr,
        6, 192,
        MM, RR * HID + RR, EE, EE, EE, RR * HID + RR, 0);

    // 9) inter + u (rounded)
    interu_kernel<<<MM / 8, 256>>>(v, hB, hA, inter, u);

    // 10) fused FFN1 + LoRA expand (1024 tiles, persistent on 444 CTAs)
    mma_gemm<96><<<dim3(PG, 1, 1), 128, DS96>>>(
        x2, r_ffn1, hbuf, ffn1_b, nullptr, inter, hA_b2,
        u, r_hAw2, RR * HID, RR * HID, RR * HID,
        nullptr, nullptr, nullptr,
        32, 1024,
        MM, FF, EE, EE, EE, FF, 3);

    // 11) out = src2 + hbuf @ ffn2^T + ffn2_b  (256 tiles)
    mma_gemm<96><<<dim3(256, 1, 1), 128, DS96>>>(
        hbuf, r_ffn2, out, ffn2_b, src2, nullptr, nullptr,
        nullptr, nullptr, 0, 0, 0, nullptr, nullptr, nullptr,
        8, 256,
        MM, EE, FF, FF, FF, EE, 0);
}

// round 17
// speedup vs baseline: 1.1599x; 1.1095x over previous
#include <cuda_runtime.h>
#include <cuda_bf16.h>
#include <math.h>
#include <stdint.h>

// Problem constants
#define BB 2
#define SS 2048
#define EE 768
#define FF 3072
#define RR 4
#define TT 128
#define HH 12
#define HD 64
#define HID 128
#define MM (BB*SS)          // 4096 tokens

// ---------------- scratch (device globals; no cudaMalloc allowed) ----------
__device__ float g_x1  [MM*EE];
__device__ float g_qkv [MM*3*EE];
__device__ float g_ctx [MM*EE];
__device__ float g_src2[MM*EE];
__device__ float g_x2  [MM*EE];
__device__ float g_hA  [MM*HID];
__device__ float g_hB  [MM*HID];
__device__ float g_WBt [(RR*HID+RR)*EE];
__device__ float g_v   [MM*(RR*HID+RR)];
__device__ float g_int [MM*RR];
__device__ float g_u   [MM*RR*HID];
__device__ float g_h   [MM*FF];
// rounded copies of GEMM operands
__device__ float g_r_task  [MM*TT];
__device__ float g_r_inproj[3*EE*EE];
__device__ float g_r_outproj[EE*EE];
__device__ float g_r_ffn1  [FF*EE];
__device__ float g_r_ffn2  [EE*FF];
__device__ float g_r_hAw2  [FF*RR*HID];
__device__ float g_r_hw1   [2*HID*TT];

// ---------------- helpers ---------------------------------------------------
__device__ __forceinline__ unsigned f2tf32(float f) {
    unsigned u;
    asm("cvt.rna.tf32.f32 %0, %1;" : "=r"(u) : "f"(f));
    return u;
}
__device__ __forceinline__ float rnd(float f) { return __uint_as_float(f2tf32(f)); }

__device__ __forceinline__ unsigned packbf(float hi, float lo) {
    unsigned r;
    asm("cvt.rn.bf16x2.f32 %0, %1, %2;" : "=r"(r) : "f"(hi), "f"(lo));
    return r;
}

__device__ __forceinline__ void mma_tf32(float c[4], const unsigned a[4], const unsigned b[2]) {
    asm volatile(
        "mma.sync.aligned.m16n8k8.row.col.f32.tf32.tf32.f32 "
        "{%0,%1,%2,%3}, {%4,%5,%6,%7}, {%8,%9}, {%0,%1,%2,%3};\n"
        : "+f"(c[0]), "+f"(c[1]), "+f"(c[2]), "+f"(c[3])
        : "r"(a[0]), "r"(a[1]), "r"(a[2]), "r"(a[3]), "r"(b[0]), "r"(b[1]));
}

__device__ __forceinline__ void mma_bf16(float c[4], const unsigned a[4], unsigned b0, unsigned b1) {
    asm volatile(
        "mma.sync.aligned.m16n8k16.row.col.f32.bf16.bf16.f32 "
        "{%0,%1,%2,%3}, {%4,%5,%6,%7}, {%8,%9}, {%0,%1,%2,%3};\n"
        : "+f"(c[0]), "+f"(c[1]), "+f"(c[2]), "+f"(c[3])
        : "r"(a[0]), "r"(a[1]), "r"(a[2]), "r"(a[3]), "r"(b0), "r"(b1));
}

// ldmatrix x4: 4 patches of 8x8 b16 (== 8x4 f32). Thread (g,t4) of patch p
// receives f32 (row g, col t4). Address lane i supplies row (i&7) of patch (i>>3).
__device__ __forceinline__ void ldsm4(unsigned& r0, unsigned& r1, unsigned& r2, unsigned& r3,
                                      unsigned addr) {
    asm volatile("ldmatrix.sync.aligned.m8n8.x4.shared.b16 {%0,%1,%2,%3}, [%4];"
        : "=r"(r0), "=r"(r1), "=r"(r2), "=r"(r3) : "r"(addr));
}

__device__ __forceinline__ void cp16(unsigned dst, const float* src) {
    asm volatile("cp.async.cg.shared.global [%0], [%1], 16;\n" :: "r"(dst), "l"(src));
}
__device__ __forceinline__ void cp16z(unsigned dst, const float* src, int sz) {
    asm volatile("cp.async.cg.shared.global [%0], [%1], 16, %2;\n" :: "r"(dst), "l"(src), "r"(sz));
}
__device__ __forceinline__ void cp_commit() { asm volatile("cp.async.commit_group;\n"); }
__device__ __forceinline__ void cp_wait0()  { asm volatile("cp.async.wait_group 0;\n"); }
__device__ __forceinline__ void cp_wait1()  { asm volatile("cp.async.wait_group 1;\n"); }

// ---------------- batched rounding pass (all weights, one launch) ----------
struct RTab {
    const float* s[8];
    float* d[8];
    int end[8];          // cumulative end, in float4 units
};

__global__ void __launch_bounds__(256) round_all(RTab t, int total4)
{
    int i = blockIdx.x * 256 + threadIdx.x;
    if (i >= total4) return;
    int j = 0;
    while (i >= t.end[j]) j++;
    int off = i - (j ? t.end[j - 1] : 0);
    float4 v = ((const float4*)t.s[j])[off];
    v.x = rnd(v.x); v.y = rnd(v.y); v.z = rnd(v.z); v.w = rnd(v.w);
    ((float4*)t.d[j])[off] = v;
}

// ---------------- rmsnorm (output rounded to tf32) --------------------------
__global__ void __launch_bounds__(256) rmsnorm_kernel(
    const float* __restrict__ x, const float* __restrict__ w, float* __restrict__ y)
{
    int row = blockIdx.x;
    const float* xr = x + (size_t)row * EE;
    float vals[3];
    float s = 0.f;
#pragma unroll
    for (int i = 0; i < 3; i++) {
        vals[i] = xr[threadIdx.x + i * 256];
        s += vals[i] * vals[i];
    }
#pragma unroll
    for (int o = 16; o; o >>= 1) s += __shfl_down_sync(0xffffffffu, s, o);
    __shared__ float red[8];
    if ((threadIdx.x & 31) == 0) red[threadIdx.x >> 5] = s;
    __syncthreads();
    if (threadIdx.x < 8) {
        float t = red[threadIdx.x];
#pragma unroll
        for (int o = 4; o; o >>= 1) t += __shfl_down_sync(0xffu, t, o);
        if (threadIdx.x == 0) red[0] = t;
    }
    __syncthreads();
    float r = rsqrtf(red[0] * (1.0f / EE) + 1.1920929e-7f);
    float* yr = y + (size_t)row * EE;
#pragma unroll
    for (int i = 0; i < 3; i++) {
        int c = threadIdx.x + i * 256;
        yr[c] = rnd(vals[i] * r * w[c]);
    }
}

// ---------------- tf32 GEMM: persistent, NT=96, 2-stage, ldmatrix fragments -
// 128 threads, 4 warps (2x2), 64m x 48n per warp.
#define ST 36
#define ATILE (128*ST)      // 4608 floats

template<int NT>
__global__ void __launch_bounds__(128, 3) mma_gemm(
    const float* __restrict__ A, const float* __restrict__ B, float* __restrict__ C,
    const float* __restrict__ bias, const float* __restrict__ res,
    const float* __restrict__ inter4, const float* __restrict__ b2,
    const float* __restrict__ A2, const float* __restrict__ B2,
    int K2, int lda2, int ldb2,
    const float* __restrict__ Bz, const float* __restrict__ biasz, float* __restrict__ Cz,
    int tilesX, int tilesTot,
    int M, int N, int K, int lda, int ldb, int ldc, int flags)
{
    constexpr int BTILE = NT * ST;
    constexpr int STG = ATILE + BTILE;
    constexpr int NWT = NT / 16;     // 6 for NT=96

    extern __shared__ float dyn[];
    if (blockIdx.z == 1) { B = Bz; bias = biasz; C = Cz; }

    const int tid  = threadIdx.x;
    const int lane = tid & 31, warp = tid >> 5;
    const int g = lane >> 2, t4 = lane & 3;
    const int wm = (warp >> 1) * 64;           // 0 or 64
    const int wn = (warp & 1) * (NT / 2);      // 0 or NT/2
    const int lr = tid >> 3;            // 0..15
    const int kA = (tid & 7) * 4;       // 0,4,..,28

    // ldmatrix addressing: lane i supplies row (i&7) of patch (i>>3)
    const int pi = lane >> 3, r8 = lane & 7;
    const int aOff = (wm + (pi & 1) * 8 + r8) * ST + (pi >> 1) * 4;   // within A tile
    const int bOff = (wn + (pi >> 1) * 8 + r8) * ST + (pi & 1) * 4;   // within B tile

    const unsigned sb = (unsigned)__cvta_generic_to_shared(dyn);

    const int n1 = K >> 5, n2 = K2 >> 5, nT = n1 + n2;
    const bool relu = flags & 1;
    const bool roundC = flags & 2;

    int mBase, nBase;

    auto issue = [&](int t, int buf) {
        const float* Ab; const float* Bb; int la, lb, k0;
        if (t < n1) { Ab = A;  Bb = B;  la = lda;  lb = ldb;  k0 = t * 32; }
        else        { Ab = A2; Bb = B2; la = lda2; lb = ldb2; k0 = (t - n1) * 32; }
#pragma unroll
        for (int r = 0; r < 8; r++) {
            int row = lr + 16 * r;
            const float* ap = Ab + (size_t)(mBase + row) * la + k0 + kA;
            cp16(sb + (buf * STG + row * ST + kA) * 4, ap);
        }
#pragma unroll
        for (int r = 0; r < NT / 16; r++) {
            int row = lr + 16 * r;
            bool ok = (nBase + row) < N;
            const float* bp = ok ? (Bb + (size_t)(nBase + row) * lb + k0 + kA) : Bb;
            cp16z(sb + (buf * STG + ATILE + row * ST + kA) * 4, bp, ok ? 16 : 0);
        }
        cp_commit();
    };

    for (int tb = blockIdx.x; tb < tilesTot; tb += gridDim.x) {
        const int bx = tb % tilesX, by = tb / tilesX;
        mBase = by * 128;
        nBase = bx * NT;

        float acc[4][NWT][4];
#pragma unroll
        for (int i = 0; i < 4; i++)
#pragma unroll
            for (int j = 0; j < NWT; j++)
#pragma unroll
                for (int c = 0; c < 4; c++) acc[i][j][c] = 0.f;

        issue(0, 0);
        if (nT > 1) issue(1, 1);

        for (int t = 0; t < nT; t++) {
            if (t < nT - 1) cp_wait1(); else cp_wait0();
            __syncthreads();

            const unsigned sA_ = sb + ((t & 1) * STG) * 4;
            const unsigned sB_ = sA_ + ATILE * 4;
#pragma unroll
            for (int kk = 0; kk < 4; kk++) {
                const int kb = kk * 8;
                unsigned a[4][4], b[NWT][2];
#pragma unroll
                for (int mt = 0; mt < 4; mt++)
                    ldsm4(a[mt][0], a[mt][1], a[mt][2], a[mt][3],
                          sA_ + (aOff + mt * 16 * ST + kb) * 4);
#pragma unroll
                for (int ntp = 0; ntp < NWT / 2; ntp++)
                    ldsm4(b[2 * ntp][0], b[2 * ntp][1], b[2 * ntp + 1][0], b[2 * ntp + 1][1],
                          sB_ + (bOff + ntp * 16 * ST + kb) * 4);
#pragma unroll
                for (int mt = 0; mt < 4; mt++)
#pragma unroll
                    for (int nt = 0; nt < NWT; nt++)
                        mma_tf32(acc[mt][nt], a[mt], b[nt]);
            }
            __syncthreads();
            if (t + 2 < nT) issue(t + 2, t & 1);
        }

#pragma unroll
        for (int mt = 0; mt < 4; mt++) {
#pragma unroll
            for (int half = 0; half < 2; half++) {
                int m = mBase + wm + mt * 16 + g + half * 8;
                float i0 = 0.f, i1 = 0.f, i2 = 0.f, i3 = 0.f;
                if (inter4) {
                    const float* ip = inter4 + (size_t)m * 4;
                    i0 = ip[0]; i1 = ip[1]; i2 = ip[2]; i3 = ip[3];
                }
#pragma unroll
                for (int nt = 0; nt < NWT; nt++) {
#pragma unroll
                    for (int c = 0; c < 2; c++) {
                        int n = nBase + wn + nt * 8 + 2 * t4 + c;
                        if (n < N) {
                            float v = acc[mt][nt][half * 2 + c];
                            if (bias) v += bias[n];
                            if (res)  v += res[(size_t)m * ldc + n];
                            if (b2) {
                                const float* bp = b2 + (size_t)n * 4;
                                v += i0 * bp[0] + i1 * bp[1] + i2 * bp[2] + i3 * bp[3];
                            }
                            if (relu) v = fmaxf(v, 0.f);
                            if (roundC) v = rnd(v);
                            C[(size_t)m * ldc + n] = v;
                        }
                    }
                }
            }
        }
    }
}

// ---------------- flash attention --------------------------------------------
// 128 threads = 4 warps; each warp owns 32 query rows (two 16-row MMA halves).
// QK tf32 with ldmatrix K fragments, PV bf16.
#define QP 68
#define VP 72
#define KVST (64*QP + 64*VP)   // 8960 floats per stage
#define FSTAGES 3
__global__ void __launch_bounds__(128, 2) flash_attn(
    const float* __restrict__ qkv, float* __restrict__ ctx)
{
    extern __shared__ float pool[];
    const unsigned sb = (unsigned)__cvta_generic_to_shared(pool);

    const int z = blockIdx.y, b = z / HH, h = z % HH;
    const float* base = qkv + (size_t)b * SS * 3 * EE + h * HD;
    const int q0 = blockIdx.x * 128;
    const int tid = threadIdx.x, lane = tid & 31, warp = tid >> 5;
    const int g = lane >> 2, t4 = lane & 3;
    const float qscale = 0.125f * 1.4426950408889634f;  // 1/sqrt(64) * log2(e)

    // ldmatrix addressing for K: patches (kc, col 0/+4), (kc+1, col 0/+4)
    const int pi = lane >> 3, r8 = lane & 7;
    const int kCol = (pi >> 1) * 8 + (pi & 1) * 4;

    // ---- stage Q (scaled, tf32) through smem: 128 rows x 64 cols
#pragma unroll
    for (int r = 0; r < 16; r++) {
        int idx = tid + r * 128;
        int row = idx >> 4, c4 = (idx & 15) * 4;
        float4 v = *(const float4*)(base + (size_t)(q0 + row) * 3 * EE + c4);
        float4 w;
        w.x = rnd(v.x * qscale);
        w.y = rnd(v.y * qscale);
        w.z = rnd(v.z * qscale);
        w.w = rnd(v.w * qscale);
        *(float4*)(pool + row * QP + c4) = w;
    }
    __syncthreads();
    unsigned qfA[8][4], qfB[8][4];
    const int wq = warp * 32;
#pragma unroll
    for (int kc = 0; kc < 8; kc++) {
        qfA[kc][0] = __float_as_uint(pool[(wq + g)      * QP + kc * 8 + t4]);
        qfA[kc][1] = __float_as_uint(pool[(wq + g + 8)  * QP + kc * 8 + t4]);
        qfA[kc][2] = __float_as_uint(pool[(wq + g)      * QP + kc * 8 + t4 + 4]);
        qfA[kc][3] = __float_as_uint(pool[(wq + g + 8)  * QP + kc * 8 + t4 + 4]);
        qfB[kc][0] = __float_as_uint(pool[(wq + g + 16) * QP + kc * 8 + t4]);
        qfB[kc][1] = __float_as_uint(pool[(wq + g + 24) * QP + kc * 8 + t4]);
        qfB[kc][2] = __float_as_uint(pool[(wq + g + 16) * QP + kc * 8 + t4 + 4]);
        qfB[kc][3] = __float_as_uint(pool[(wq + g + 24) * QP + kc * 8 + t4 + 4]);
    }
    __syncthreads();

    float oA[8][4], oB[8][4];
#pragma unroll
    for (int v = 0; v < 8; v++)
#pragma unroll
        for (int c = 0; c < 4; c++) { oA[v][c] = 0.f; oB[v][c] = 0.f; }
    float lA0 = 0.f, lA1 = 0.f, lB0 = 0.f, lB1 = 0.f;

    const int frow = tid >> 4, fseg = (tid & 15) * 4;

    auto issue_kv = [&](int kt, int buf) {
#pragma unroll
        for (int r = 0; r < 8; r++) {
            int row = frow + r * 8;
            const float* kp = base + EE     + (size_t)(kt * 64 + row) * 3 * EE + fseg;
            const float* vp = base + 2 * EE + (size_t)(kt * 64 + row) * 3 * EE + fseg;
            cp16(sb + (buf * KVST + row * QP + fseg) * 4, kp);
            cp16(sb + (buf * KVST + 64 * QP + row * VP + fseg) * 4, vp);
        }
        cp_commit();
    };

    const int NKT = SS / 64;
    issue_kv(0, 0);
    issue_kv(1, 1);

    for (int kt = 0; kt < NKT; kt++) {
        if (kt < NKT - 1) cp_wait1(); else cp_wait0();
        __syncthreads();
        if (kt + 2 < NKT) issue_kv(kt + 2, (kt + 2) % FSTAGES);

        const unsigned kroot = sb + ((kt % FSTAGES) * KVST) * 4;
        const float* Vs = pool + (kt % FSTAGES) * KVST + 64 * QP;

        // ---- scores: K fragments via ldmatrix (2 kc per ldsm4)
        float sA[8][4], sB[8][4];
#pragma unroll
        for (int j = 0; j < 8; j++)
#pragma unroll
            for (int c = 0; c < 4; c++) { sA[j][c] = 0.f; sB[j][c] = 0.f; }
#pragma unroll
        for (int j = 0; j < 8; j++) {
            const unsigned rowaddr = kroot + ((j * 8 + r8) * QP + kCol) * 4;
#pragma unroll
            for (int kc2 = 0; kc2 < 4; kc2++) {
                unsigned bfr0[2], bfr1[2];
                ldsm4(bfr0[0], bfr0[1], bfr1[0], bfr1[1], rowaddr + kc2 * 16 * 4);
                mma_tf32(sA[j], qfA[2 * kc2],     bfr0);
                mma_tf32(sB[j], qfB[2 * kc2],     bfr0);
                mma_tf32(sA[j], qfA[2 * kc2 + 1], bfr1);
                mma_tf32(sB[j], qfB[2 * kc2 + 1], bfr1);
            }
        }

        // ---- max-free softmax: p = exp2(s) (scores bounded; fp32-safe)
#pragma unroll
        for (int j = 0; j < 8; j++) {
            sA[j][0] = exp2f(sA[j][0]); sA[j][1] = exp2f(sA[j][1]);
            sA[j][2] = exp2f(sA[j][2]); sA[j][3] = exp2f(sA[j][3]);
            lA0 += sA[j][0] + sA[j][1];
            lA1 += sA[j][2] + sA[j][3];
            sB[j][0] = exp2f(sB[j][0]); sB[j][1] = exp2f(sB[j][1]);
            sB[j][2] = exp2f(sB[j][2]); sB[j][3] = exp2f(sB[j][3]);
            lB0 += sB[j][0] + sB[j][1];
            lB1 += sB[j][2] + sB[j][3];
        }

        // ---- P.V in bf16 m16n8k16, sharing V fragments between halves
#pragma unroll
        for (int j2 = 0; j2 < 4; j2++) {
            unsigned paA[4], paB[4];
            paA[0] = packbf(sA[2 * j2][1],     sA[2 * j2][0]);
            paA[1] = packbf(sA[2 * j2][3],     sA[2 * j2][2]);
            paA[2] = packbf(sA[2 * j2 + 1][1], sA[2 * j2 + 1][0]);
            paA[3] = packbf(sA[2 * j2 + 1][3], sA[2 * j2 + 1][2]);
            paB[0] = packbf(sB[2 * j2][1],     sB[2 * j2][0]);
            paB[1] = packbf(sB[2 * j2][3],     sB[2 * j2][2]);
            paB[2] = packbf(sB[2 * j2 + 1][1], sB[2 * j2 + 1][0]);
            paB[3] = packbf(sB[2 * j2 + 1][3], sB[2 * j2 + 1][2]);
            const float* vr0 = Vs + (j2 * 16 + 2 * t4) * VP;
            const float* vr1 = vr0 + VP;
            const float* vr2 = vr0 + 8 * VP;
            const float* vr3 = vr2 + VP;
#pragma unroll
            for (int v = 0; v < 8; v++) {
                int d = v * 8 + g;
                unsigned b0 = packbf(vr1[d], vr0[d]);
                unsigned b1 = packbf(vr3[d], vr2[d]);
                mma_bf16(oA[v], paA, b0, b1);
                mma_bf16(oB[v], paB, b0, b1);
            }
        }
    }

    // ---- finalize (rounded: ctx feeds out_proj GEMM)
    lA0 += __shfl_xor_sync(0xffffffffu, lA0, 1);
    lA0 += __shfl_xor_sync(0xffffffffu, lA0, 2);
    lA1 += __shfl_xor_sync(0xffffffffu, lA1, 1);
    lA1 += __shfl_xor_sync(0xffffffffu, lA1, 2);
    lB0 += __shfl_xor_sync(0xffffffffu, lB0, 1);
    lB0 += __shfl_xor_sync(0xffffffffu, lB0, 2);
    lB1 += __shfl_xor_sync(0xffffffffu, lB1, 1);
    lB1 += __shfl_xor_sync(0xffffffffu, lB1, 2);
    float iA0 = 1.f / lA0, iA1 = 1.f / lA1, iB0 = 1.f / lB0, iB1 = 1.f / lB1;
    int row0 = q0 + wq + g;
    float* c0p = ctx + ((size_t)(b * SS + row0))      * EE + h * HD;
    float* c1p = ctx + ((size_t)(b * SS + row0 + 8))  * EE + h * HD;
    float* c2p = ctx + ((size_t)(b * SS + row0 + 16)) * EE + h * HD;
    float* c3p = ctx + ((size_t)(b * SS + row0 + 24)) * EE + h * HD;
#pragma unroll
    for (int v = 0; v < 8; v++) {
        int col = v * 8 + 2 * t4;
        *(float2*)(c0p + col) = make_float2(rnd(oA[v][0] * iA0), rnd(oA[v][1] * iA0));
        *(float2*)(c1p + col) = make_float2(rnd(oA[v][2] * iA1), rnd(oA[v][3] * iA1));
        *(float2*)(c2p + col) = make_float2(rnd(oB[v][0] * iB0), rnd(oB[v][1] * iB0));
        *(float2*)(c3p + col) = make_float2(rnd(oB[v][2] * iB1), rnd(oB[v][3] * iB1));
    }
}

// ---------------- small helper kernels -------------------------------------
__global__ void build_WBt(const float* __restrict__ hB_w2,
                          const float* __restrict__ hB_b2,
                          float* __restrict__ WBt)
{
    int idx = blockIdx.x * 256 + threadIdx.x;
    if (idx >= (RR * HID + RR) * EE) return;
    int n = idx / EE, e = idx % EE;
    float val;
    if (n < RR * HID) {
        int r = n >> 7, h = n & 127;
        val = hB_w2[((size_t)(r * EE + e)) * HID + h];
    } else {
        val = hB_b2[(n - RR * HID) * EE + e];
    }
    WBt[idx] = rnd(val);
}

__global__ void __launch_bounds__(256) interu_kernel(
    const float* __restrict__ v, const float* __restrict__ hB,
    const float* __restrict__ hA, float* __restrict__ inter, float* __restrict__ u)
{
    int wtok = (blockIdx.x * 256 + threadIdx.x) >> 5;
    int lane = threadIdx.x & 31;
    if (wtok >= MM) return;
    const float* vr = v + (size_t)wtok * (RR * HID + RR);
    const float* br = hB + (size_t)wtok * HID;
    float hb[4], ha[4];
#pragma unroll
    for (int j = 0; j < 4; j++) {
        hb[j] = br[lane + j * 32];
        ha[j] = hA[(size_t)wtok * HID + lane + j * 32];
    }
    float iv[RR];
#pragma unroll
    for (int r = 0; r < RR; r++) {
        float s = 0.f;
#pragma unroll
        for (int j = 0; j < 4; j++) s += hb[j] * vr[r * HID + lane + j * 32];
#pragma unroll
        for (int o = 16; o; o >>= 1) s += __shfl_xor_sync(0xffffffffu, s, o);
        iv[r] = s + vr[RR * HID + r];
    }
    if (lane < RR) inter[wtok * RR + lane] = iv[lane];
    float* ur = u + (size_t)wtok * RR * HID;
#pragma unroll
    for (int r = 0; r < RR; r++)
#pragma unroll
        for (int j = 0; j < 4; j++)
            ur[r * HID + lane + j * 32] = rnd(iv[r] * ha[j]);
}

// ---------------- launch ----------------------------------------------------
extern "C" void kernel_launch(void* const* d_in, const int* in_sizes, int n_in,
                              void* d_out, int out_size)
{
    const float* src       = (const float*)d_in[0];
    const float* task      = (const float*)d_in[1];
    const float* norm1_w   = (const float*)d_in[2];
    const float* norm2_w   = (const float*)d_in[3];
    const float* in_proj_w = (const float*)d_in[4];
    const float* out_proj_w= (const float*)d_in[5];
    const float* ffn1_w    = (const float*)d_in[6];
    const float* ffn1_b    = (const float*)d_in[7];
    const float* ffn2_w    = (const float*)d_in[8];
    const float* ffn2_b    = (const float*)d_in[9];
    const float* hA_w1     = (const float*)d_in[10];
    const float* hA_b1     = (const float*)d_in[11];
    const float* hA_w2     = (const float*)d_in[12];
    const float* hA_b2     = (const float*)d_in[13];
    const float* hB_w1     = (const float*)d_in[14];
    const float* hB_b1     = (const float*)d_in[15];
    const float* hB_w2     = (const float*)d_in[16];
    const float* hB_b2     = (const float*)d_in[17];
    float* out = (float*)d_out;

    float *x1, *qkv, *ctx, *src2, *x2, *hA, *hB, *WBt, *v, *inter, *u, *hbuf;
    float *r_task, *r_inproj, *r_outproj, *r_ffn1, *r_ffn2, *r_hAw2, *r_hw1;
    cudaGetSymbolAddress((void**)&x1,   g_x1);
    cudaGetSymbolAddress((void**)&qkv,  g_qkv);
    cudaGetSymbolAddress((void**)&ctx,  g_ctx);
    cudaGetSymbolAddress((void**)&src2, g_src2);
    cudaGetSymbolAddress((void**)&x2,   g_x2);
    cudaGetSymbolAddress((void**)&hA,   g_hA);
    cudaGetSymbolAddress((void**)&hB,   g_hB);
    cudaGetSymbolAddress((void**)&WBt,  g_WBt);
    cudaGetSymbolAddress((void**)&v,    g_v);
    cudaGetSymbolAddress((void**)&inter,g_int);
    cudaGetSymbolAddress((void**)&u,    g_u);
    cudaGetSymbolAddress((void**)&hbuf, g_h);
    cudaGetSymbolAddress((void**)&r_task,   g_r_task);
    cudaGetSymbolAddress((void**)&r_inproj, g_r_inproj);
    cudaGetSymbolAddress((void**)&r_outproj,g_r_outproj);
    cudaGetSymbolAddress((void**)&r_ffn1,   g_r_ffn1);
    cudaGetSymbolAddress((void**)&r_ffn2,   g_r_ffn2);
    cudaGetSymbolAddress((void**)&r_hAw2,   g_r_hAw2);
    cudaGetSymbolAddress((void**)&r_hw1,    g_r_hw1);

    const int DS96 = 2 * (ATILE + 96 * ST) * 4;     // 64512 B (2-stage)
    const int FS = FSTAGES * KVST * 4;              // 107520 B
    cudaFuncSetAttribute(mma_gemm<96>, cudaFuncAttributeMaxDynamicSharedMemorySize, DS96);
    cudaFuncSetAttribute(flash_attn,   cudaFuncAttributeMaxDynamicSharedMemorySize, FS);

    const int PG = 444;   // 3 CTAs/SM x 148 SMs

    // 0) pre-round all GEMM operands to tf32 (one launch)
    {
        RTab t;
        const float* ss[8] = {task, in_proj_w, out_proj_w, ffn1_w, ffn2_w, hA_w2, hA_w1, hB_w1};
        float* dd[8] = {r_task, r_inproj, r_outproj, r_ffn1, r_ffn2, r_hAw2, r_hw1, r_hw1 + HID * TT};
        int nn[8] = {MM * TT / 4, 3 * EE * EE / 4, EE * EE / 4, FF * EE / 4,
                     EE * FF / 4, FF * RR * HID / 4, HID * TT / 4, HID * TT / 4};
        int cum = 0;
        for (int j = 0; j < 8; j++) { t.s[j] = ss[j]; t.d[j] = dd[j]; cum += nn[j]; t.end[j] = cum; }
        round_all<<<(cum + 255) / 256, 256>>>(t, cum);
    }

    // 1) x1 = rmsnorm(src, norm1_w) (rounded)
    rmsnorm_kernel<<<MM, 256>>>(src, norm1_w, x1);

    // 2) qkv = x1 @ in_proj^T (768 tiles, persistent on 444 CTAs)
    mma_gemm<96><<<dim3(PG, 1, 1), 128, DS96>>>(
        x1, r_inproj, qkv, nullptr, nullptr, nullptr, nullptr,
        nullptr, nullptr, 0, 0, 0, nullptr, nullptr, nullptr,
        24, 768,
        MM, 3 * EE, EE, EE, EE, 3 * EE, 2);

    // 3) flash attention -> ctx (rounded); 128 threads, 4 warps x 32 q-rows
    flash_attn<<<dim3(SS / 128, BB * HH), 128, FS>>>(qkv, ctx);

    // 4) src2 = src + ctx @ out_proj^T  (256 tiles)
    mma_gemm<96><<<dim3(256, 1, 1), 128, DS96>>>(
        ctx, r_outproj, src2, nullptr, src, nullptr, nullptr,
        nullptr, nullptr, 0, 0, 0, nullptr, nullptr, nullptr,
        8, 256,
        MM, EE, EE, EE, EE, EE, 0);

    // 5) x2 = rmsnorm(src2) (rounded)
    rmsnorm_kernel<<<MM, 256>>>(src2, norm2_w, x2);

    // 6) hypernet hiddens hA & hB in one launch (z selects problem; 64 tiles each)
    mma_gemm<96><<<dim3(64, 1, 2), 128, DS96>>>(
        r_task, r_hw1, hA, hA_b1, nullptr, nullptr, nullptr,
        nullptr, nullptr, 0, 0, 0,
        r_hw1 + HID * TT, hB_b1, hB,
        2, 64,
        MM, HID, TT, TT, TT, HID, 1);

    // 7) rearranged B-side weights (rounded)
    build_WBt<<<((RR * HID + RR) * EE + 255) / 256, 256>>>(hB_w2, hB_b2, WBt);

    // 8) v = x2 @ WBt^T  [4096, 516]  (192 tiles)
    mma_gemm<96><<<dim3(192, 1, 1), 128, DS96>>>(
        x2, WBt, v, nullptr, nullptr, nullptr, nullptr,
        nullptr, nullptr, 0, 0, 0, nullptr, nullptr, nullptr,
        6, 192,
        MM, RR * HID + RR, EE, EE, EE, RR * HID + RR, 0);

    // 9) inter + u (rounded)
    interu_kernel<<<MM / 8, 256>>>(v, hB, hA, inter, u);

    // 10) fused FFN1 + LoRA expand (1024 tiles, persistent on 444 CTAs)
    mma_gemm<96><<<dim3(PG, 1, 1), 128, DS96>>>(
        x2, r_ffn1, hbuf, ffn1_b, nullptr, inter, hA_b2,
        u, r_hAw2, RR * HID, RR * HID, RR * HID,
        nullptr, nullptr, nullptr,
        32, 1024,
        MM, FF, EE, EE, EE, FF, 3);

    // 11) out = src2 + hbuf @ ffn2^T + ffn2_b  (256 tiles)
    mma_gemm<96><<<dim3(256, 1, 1), 128, DS96>>>(
        hbuf, r_ffn2, out, ffn2_b, src2, nullptr, nullptr,
        nullptr, nullptr, 0, 0, 0, nullptr, nullptr, nullptr,
        8, 256,
        MM, EE, FF, FF, FF, EE, 0);
}